// round 2
// baseline (speedup 1.0000x reference)
#include <cuda_runtime.h>
#include <math.h>

#define NN 50000
#define NE 1000000
#define HH 128

__device__ float g_x[NN * HH];    // node features
__device__ float g_xm[NN * HH];   // swish(x@W_msg); later xe
__device__ float g_agg[NN * HH];  // scatter target; later h0

__device__ __forceinline__ float swishf(float v) { return v / (1.f + expf(-v)); }

struct F3 { float x, y, z; };
__device__ __forceinline__ F3 mk3(float a, float b, float c) { F3 r; r.x=a; r.y=b; r.z=c; return r; }
__device__ __forceinline__ F3 sub3(F3 a, F3 b) { return mk3(a.x-b.x, a.y-b.y, a.z-b.z); }
__device__ __forceinline__ F3 crs3(F3 a, F3 b) {
    return mk3(a.y*b.z - a.z*b.y, a.z*b.x - a.x*b.z, a.x*b.y - a.y*b.x);
}
__device__ __forceinline__ float dot3(F3 a, F3 b) { return a.x*b.x + a.y*b.y + a.z*b.z; }
__device__ __forceinline__ F3 ld3(const float* __restrict__ p, int i) {
    return mk3(p[3*i], p[3*i+1], p[3*i+2]);
}

__global__ void k_zero() {
    int i = blockIdx.x * 256 + threadIdx.x;
    ((float4*)g_agg)[i] = make_float4(0.f, 0.f, 0.f, 0.f);
}

// x[:,0:64] = [onehot(z), bb, sc] @ W_emb + b_emb
__global__ void k_embed(const int* __restrict__ z, const float* __restrict__ bb,
                        const float* __restrict__ sc, const float* __restrict__ W,
                        const float* __restrict__ b) {
    __shared__ float sW[40 * 64];
    __shared__ float sb[64];
    int tid = threadIdx.x;
    for (int idx = tid; idx < 40 * 64; idx += 256) sW[idx] = W[idx];
    if (tid < 64) sb[tid] = b[tid];
    __syncthreads();
    int n = blockIdx.x * 4 + (tid >> 6);
    int c = tid & 63;
    if (n < NN) {
        float acc = sb[c] + sW[z[n] * 64 + c];
        #pragma unroll
        for (int q = 0; q < 6; q++) acc += bb[n * 6 + q] * sW[(26 + q) * 64 + c];
        #pragma unroll
        for (int q = 0; q < 8; q++) acc += sc[n * 8 + q] * sW[(32 + q) * 64 + c];
        g_x[n * HH + c] = acc;
    }
}

// x[:,64:128] = esm @ W_esm + b_esm   (64-row x 64-col tiles)
__global__ void __launch_bounds__(256) k_esm(const float* __restrict__ esm,
                                             const float* __restrict__ W,
                                             const float* __restrict__ b) {
    __shared__ __align__(16) float As[32][68];
    __shared__ __align__(16) float Bs[32][64];
    int tid = threadIdx.x;
    int m0 = blockIdx.x * 64;
    int ty = tid >> 4, tx = tid & 15;
    float acc[4][4] = {};
    for (int k0 = 0; k0 < 1280; k0 += 32) {
        #pragma unroll
        for (int it = 0; it < 8; it++) {
            int idx = it * 256 + tid;
            int m = idx >> 5, k = idx & 31;
            int row = m0 + m; if (row >= NN) row = NN - 1;
            As[k][m] = esm[row * 1280 + k0 + k];
        }
        #pragma unroll
        for (int it = 0; it < 8; it++) {
            int idx = it * 256 + tid;
            int k = idx >> 6, c = idx & 63;
            Bs[k][c] = W[(k0 + k) * 64 + c];
        }
        __syncthreads();
        #pragma unroll 8
        for (int k = 0; k < 32; k++) {
            float4 av = *(const float4*)&As[k][ty * 4];
            float4 bv = *(const float4*)&Bs[k][tx * 4];
            float ar[4] = {av.x, av.y, av.z, av.w};
            float br[4] = {bv.x, bv.y, bv.z, bv.w};
            #pragma unroll
            for (int mm = 0; mm < 4; mm++)
                #pragma unroll
                for (int cc = 0; cc < 4; cc++) acc[mm][cc] += ar[mm] * br[cc];
        }
        __syncthreads();
    }
    #pragma unroll
    for (int mm = 0; mm < 4; mm++) {
        int row = m0 + ty * 4 + mm;
        if (row < NN) {
            #pragma unroll
            for (int cc = 0; cc < 4; cc++)
                g_x[row * HH + 64 + tx * 4 + cc] = acc[mm][cc] + b[tx * 4 + cc];
        }
    }
}

// [N,128]@[128,128] 64-row tiles.  EPI0: xm=swish(x@W)  EPI1: xe=x+swish(agg@W)
// EPI2: h0=relu(xe@W+bias) -> g_agg
template <int EPI>
__global__ void __launch_bounds__(256) k_gemm128(const float* __restrict__ W,
                                                 const float* __restrict__ bias) {
    extern __shared__ float sm[];
    float* Xs = sm;               // 128*68 [k][m]
    float* Ws = sm + 128 * 68;    // 128*128 [k][c]
    int tid = threadIdx.x;
    int m0 = blockIdx.x * 64;
    const float* A = (EPI == 0) ? g_x : (EPI == 1) ? g_agg : g_xm;
    float* O = (EPI == 2) ? g_agg : g_xm;
    for (int idx = tid; idx < 128 * 128; idx += 256) Ws[idx] = W[idx];
    #pragma unroll
    for (int it = 0; it < 32; it++) {
        int idx = it * 256 + tid;
        int m = idx >> 7, k = idx & 127;
        int row = m0 + m; if (row >= NN) row = NN - 1;
        Xs[k * 68 + m] = A[row * HH + k];
    }
    __syncthreads();
    int ty = tid >> 4, tx = tid & 15;
    float acc[4][8] = {};
    #pragma unroll 8
    for (int k = 0; k < 128; k++) {
        float4 av = *(const float4*)&Xs[k * 68 + ty * 4];
        float4 b0 = *(const float4*)&Ws[k * 128 + tx * 8];
        float4 b1 = *(const float4*)&Ws[k * 128 + tx * 8 + 4];
        float ar[4] = {av.x, av.y, av.z, av.w};
        float br[8] = {b0.x, b0.y, b0.z, b0.w, b1.x, b1.y, b1.z, b1.w};
        #pragma unroll
        for (int mm = 0; mm < 4; mm++)
            #pragma unroll
            for (int cc = 0; cc < 8; cc++) acc[mm][cc] += ar[mm] * br[cc];
    }
    #pragma unroll
    for (int mm = 0; mm < 4; mm++) {
        int row = m0 + ty * 4 + mm;
        if (row < NN) {
            #pragma unroll
            for (int cc = 0; cc < 8; cc++) {
                int c = tx * 8 + cc;
                float v;
                if (EPI == 2) v = fmaxf(acc[mm][cc] + bias[c], 0.f);
                else if (EPI == 1) v = g_x[row * HH + c] + swishf(acc[mm][cc]);
                else v = swishf(acc[mm][cc]);
                O[row * HH + c] = v;
            }
        }
    }
}

// fused edge kernel: 64 edges/block
__global__ void __launch_bounds__(256) k_edge(const int* __restrict__ ei,
                                              const float* __restrict__ pos,
                                              const float* __restrict__ posn,
                                              const float* __restrict__ posc,
                                              const float* __restrict__ We) {
    extern __shared__ float sm[];
    float* Ws = sm;                          // 124*128
    float* Fs = sm + 124 * 128;              // 124*68 [k][e]
    int* js = (int*)(sm + 124 * 128 + 124 * 68);
    int* is_ = js + 64;
    float* freqs = (float*)(is_ + 64);       // 8
    int tid = threadIdx.x;
    for (int idx = tid; idx < 124 * 128; idx += 256) Ws[idx] = We[idx];
    if (tid < 8) {
        float t = (float)(2 * tid) * (float)(-0.5756462732485115);
        freqs[tid] = (float)exp((double)t);
    }
    __syncthreads();
    if (tid < 64) {
        int e = blockIdx.x * 64 + tid;
        int j = ei[e], i = ei[NE + e];
        js[tid] = j; is_[tid] = i;
        F3 pi_ = ld3(pos, i), pj = ld3(pos, j);
        F3 vji = sub3(pj, pi_);
        float dist = sqrtf(dot3(vji, vji));
        int r0 = (i == 0) ? NN - 1 : i - 1;
        int r1 = (i == NN - 1) ? 0 : i + 1;
        F3 vr0 = sub3(ld3(pos, r0), pi_);
        F3 vr1 = sub3(ld3(pos, r1), pi_);
        float a = dot3(vji, vr0);
        F3 cr = crs3(vji, vr0);
        float b2 = dot3(cr, cr);
        float ct1 = a * rsqrtf(fmaxf(a * a + b2, 1e-30f));
        float ct2 = 2.f * ct1 * ct1 - 1.f;
        F3 p1 = crs3(vr0, vr1), p2 = crs3(vr0, vji);
        float ap = dot3(p1, p2);
        F3 c12 = crs3(p1, p2);
        float bp = dot3(c12, vr0) / (sqrtf(dot3(vr0, vr0)) + 1e-7f);
        float cp1 = ap * rsqrtf(fmaxf(ap * ap + bp * bp, 1e-30f));
        float cp2 = 2.f * cp1 * cp1 - 1.f;
        F3 o1x = sub3(ld3(posn, i), pi_);
        F3 o1z = crs3(o1x, crs3(o1x, sub3(ld3(posc, i), pi_)));
        float o1zl = sqrtf(dot3(o1z, o1z)) + 1e-7f;
        F3 o2x = sub3(ld3(posn, j), pj);
        F3 o2z = crs3(o2x, crs3(o2x, sub3(ld3(posc, j), pj)));
        float o2zl = sqrtf(dot3(o2z, o2z)) + 1e-7f;
        F3 nv = crs3(o1z, o2z);
        float a1 = dot3(o1x, nv);
        float b1 = dot3(crs3(o1x, nv), o1z) / o1zl;
        float cA10 = a1 * rsqrtf(fmaxf(a1 * a1 + b1 * b1, 1e-30f));
        float cA11 = 2.f * cA10 * cA10 - 1.f;
        float a2 = dot3(o1z, o2z);
        float b2v = sqrtf(dot3(nv, nv));
        float cA20 = a2 * rsqrtf(fmaxf(a2 * a2 + b2v * b2v, 1e-30f));
        float cA21 = 2.f * cA20 * cA20 - 1.f;
        float a3 = dot3(nv, o2x);
        float b3 = dot3(crs3(nv, o2x), o2z) / o2zl;
        float cA30 = a3 * rsqrtf(fmaxf(a3 * a3 + b3 * b3, 1e-30f));
        float cA31 = 2.f * cA30 * cA30 - 1.f;
        float u = fminf(dist / 11.5f, 1.f);
        float fc = 0.5f * (cosf(3.14159274f * u) + 1.f);
        float rs = (float)0.41702882811414954 * fc / (dist + 1e-6f);
        float r[6];
        #pragma unroll
        for (int n = 0; n < 6; n++)
            r[n] = rs * sinf((float)(n + 1) * 3.14159274f * u);
        float ct[3] = {1.f, ct1, ct2};
        float cp[3] = {1.f, cp1, cp2};
        #pragma unroll
        for (int n = 0; n < 6; n++)
            #pragma unroll
            for (int l = 0; l < 3; l++) {
                float rl = r[n] * ct[l];
                #pragma unroll
                for (int m = 0; m < 3; m++)
                    Fs[(n * 9 + l * 3 + m) * 68 + tid] = rl * cp[m];
            }
        float cA[3][3] = {{1.f, cA10, cA11}, {1.f, cA20, cA21}, {1.f, cA30, cA31}};
        #pragma unroll
        for (int t = 0; t < 3; t++)
            #pragma unroll
            for (int n = 0; n < 6; n++)
                #pragma unroll
                for (int l = 0; l < 3; l++)
                    Fs[(54 + t * 18 + n * 3 + l) * 68 + tid] = r[n] * cA[t][l];
        float dpe = (float)(j - i);
        #pragma unroll
        for (int kk = 0; kk < 8; kk++) {
            float s, c;
            sincosf(dpe * freqs[kk], &s, &c);
            Fs[(108 + kk) * 68 + tid] = c;
            Fs[(116 + kk) * 68 + tid] = s;
        }
    }
    __syncthreads();
    int eg = tid >> 4, cg = tid & 15;
    float acc[4][8] = {};
    #pragma unroll 4
    for (int k = 0; k < 124; k++) {
        float4 av = *(const float4*)&Fs[k * 68 + eg * 4];
        float4 b0 = *(const float4*)&Ws[k * 128 + cg * 8];
        float4 b1 = *(const float4*)&Ws[k * 128 + cg * 8 + 4];
        float ar[4] = {av.x, av.y, av.z, av.w};
        float br[8] = {b0.x, b0.y, b0.z, b0.w, b1.x, b1.y, b1.z, b1.w};
        #pragma unroll
        for (int mm = 0; mm < 4; mm++)
            #pragma unroll
            for (int cc = 0; cc < 8; cc++) acc[mm][cc] += ar[mm] * br[cc];
    }
    #pragma unroll
    for (int mm = 0; mm < 4; mm++) {
        int el = eg * 4 + mm;
        int j = js[el], i = is_[el];
        const float* xr = g_xm + j * HH + cg * 8;
        float* ar = g_agg + i * HH + cg * 8;
        float4 x0 = *(const float4*)xr;
        float4 x1 = *(const float4*)(xr + 4);
        float m0v = swishf(acc[mm][0]) * x0.x;
        float m1v = swishf(acc[mm][1]) * x0.y;
        float m2v = swishf(acc[mm][2]) * x0.z;
        float m3v = swishf(acc[mm][3]) * x0.w;
        float m4v = swishf(acc[mm][4]) * x1.x;
        float m5v = swishf(acc[mm][5]) * x1.y;
        float m6v = swishf(acc[mm][6]) * x1.z;
        float m7v = swishf(acc[mm][7]) * x1.w;
        asm volatile("red.global.add.v4.f32 [%0], {%1,%2,%3,%4};"
                     :: "l"(ar), "f"(m0v), "f"(m1v), "f"(m2v), "f"(m3v) : "memory");
        asm volatile("red.global.add.v4.f32 [%0], {%1,%2,%3,%4};"
                     :: "l"(ar + 4), "f"(m4v), "f"(m5v), "f"(m6v), "f"(m7v) : "memory");
    }
}

// node head: one warp per node
__global__ void __launch_bounds__(256) k_nodehead(const float* __restrict__ W0,
                                                  const float* __restrict__ b0,
                                                  const float* __restrict__ Wf,
                                                  const float* __restrict__ bf,
                                                  float* __restrict__ out2) {
    __shared__ float sW[4096];
    __shared__ float sb[32], sWf[64], sbf[2];
    int tid = threadIdx.x;
    for (int idx = tid; idx < 4096; idx += 256) sW[idx] = W0[idx];
    if (tid < 32) sb[tid] = b0[tid];
    if (tid < 64) sWf[tid] = Wf[tid];
    if (tid < 2) sbf[tid] = bf[tid];
    __syncthreads();
    int w = tid >> 5, lane = tid & 31;
    int n = blockIdx.x * 8 + w;
    if (n >= NN) return;
    const float* xr = g_x + n * HH;
    float acc = sb[lane];
    #pragma unroll 8
    for (int k = 0; k < 128; k++) acc += xr[k] * sW[k * 32 + lane];
    float xn = fmaxf(acc, 0.f);
    float v0 = xn * sWf[lane * 2], v1 = xn * sWf[lane * 2 + 1];
    #pragma unroll
    for (int off = 16; off > 0; off >>= 1) {
        v0 += __shfl_xor_sync(0xffffffffu, v0, off);
        v1 += __shfl_xor_sync(0xffffffffu, v1, off);
    }
    if (lane == 0) { out2[n * 2] = v0 + sbf[0]; out2[n * 2 + 1] = v1 + sbf[1]; }
}

// final head: out = sigmoid(relu(h0@W_o1+b)@W_of+b)  (h0 in g_agg)
__global__ void __launch_bounds__(256) k_final(const float* __restrict__ W1,
                                               const float* __restrict__ b1,
                                               const float* __restrict__ Wf,
                                               const float* __restrict__ bf,
                                               float* __restrict__ out) {
    __shared__ float sW[4096];
    __shared__ float sb[32], sWf[32];
    int tid = threadIdx.x;
    for (int idx = tid; idx < 4096; idx += 256) sW[idx] = W1[idx];
    if (tid < 32) { sb[tid] = b1[tid]; sWf[tid] = Wf[tid]; }
    __syncthreads();
    int w = tid >> 5, lane = tid & 31;
    int n = blockIdx.x * 8 + w;
    if (n >= NN) return;
    const float* hr = g_agg + n * HH;
    float acc = sb[lane];
    #pragma unroll 8
    for (int k = 0; k < 128; k++) acc += hr[k] * sW[k * 32 + lane];
    float v = fmaxf(acc, 0.f) * sWf[lane];
    #pragma unroll
    for (int off = 16; off > 0; off >>= 1) v += __shfl_xor_sync(0xffffffffu, v, off);
    if (lane == 0) out[n] = 1.f / (1.f + expf(-(v + bf[0])));
}

extern "C" void kernel_launch(void* const* d_in, const int* in_sizes, int n_in,
                              void* d_out, int out_size) {
    const int* z = (const int*)d_in[0];
    const float* pos = (const float*)d_in[1];
    const float* posn = (const float*)d_in[2];
    const float* posc = (const float*)d_in[3];
    const float* bb = (const float*)d_in[4];
    const float* sc = (const float*)d_in[5];
    const float* esm = (const float*)d_in[6];
    const int* ei = (const int*)d_in[8];
    const float* W_emb = (const float*)d_in[9];
    const float* b_emb = (const float*)d_in[10];
    const float* W_esm = (const float*)d_in[11];
    const float* b_esm = (const float*)d_in[12];
    const float* W_edge = (const float*)d_in[13];
    const float* W_msg = (const float*)d_in[14];
    const float* W_upd = (const float*)d_in[15];
    const float* W_o0 = (const float*)d_in[16];
    const float* b_o0 = (const float*)d_in[17];
    const float* W_o1 = (const float*)d_in[18];
    const float* b_o1 = (const float*)d_in[19];
    const float* W_of = (const float*)d_in[20];
    const float* b_of = (const float*)d_in[21];
    const float* W_n0 = (const float*)d_in[22];
    const float* b_n0 = (const float*)d_in[23];
    const float* W_nf = (const float*)d_in[24];
    const float* b_nf = (const float*)d_in[25];
    float* out = (float*)d_out;

    static bool attr_done = false;
    if (!attr_done) {
        cudaFuncSetAttribute(k_gemm128<0>, cudaFuncAttributeMaxDynamicSharedMemorySize, 100352);
        cudaFuncSetAttribute(k_gemm128<1>, cudaFuncAttributeMaxDynamicSharedMemorySize, 100352);
        cudaFuncSetAttribute(k_gemm128<2>, cudaFuncAttributeMaxDynamicSharedMemorySize, 100352);
        cudaFuncSetAttribute(k_edge, cudaFuncAttributeMaxDynamicSharedMemorySize, 97760);
        attr_done = true;
    }

    k_zero<<<6250, 256>>>();
    k_embed<<<12500, 256>>>(z, bb, sc, W_emb, b_emb);
    k_esm<<<782, 256>>>(esm, W_esm, b_esm);
    k_gemm128<0><<<782, 256, 100352>>>(W_msg, nullptr);
    k_edge<<<15625, 256, 97760>>>(ei, pos, posn, posc, W_edge);
    k_gemm128<1><<<782, 256, 100352>>>(W_upd, nullptr);
    k_gemm128<2><<<782, 256, 100352>>>(W_o0, b_o0);
    k_nodehead<<<6250, 256>>>(W_n0, b_n0, W_nf, b_nf, out + NN);
    k_final<<<6250, 256>>>(W_o1, b_o1, W_of, b_of, out);
}

// round 3
// speedup vs baseline: 1.5906x; 1.5906x over previous
#include <cuda_runtime.h>
#include <math.h>

#define NN 50000
#define NE 1000000
#define HH 128

__device__ float g_x[NN * HH];    // node features
__device__ float g_xm[NN * HH];   // swish(x@W_msg); later xe
__device__ float g_agg[NN * HH];  // scatter target; later h0
__device__ int g_ncnt, g_fcnt;
__device__ int2 g_nJI[NE];
__device__ int2 g_fJI[NE];

__device__ __forceinline__ float swishf(float v) { return v / (1.f + expf(-v)); }

struct F3 { float x, y, z; };
__device__ __forceinline__ F3 mk3(float a, float b, float c) { F3 r; r.x=a; r.y=b; r.z=c; return r; }
__device__ __forceinline__ F3 sub3(F3 a, F3 b) { return mk3(a.x-b.x, a.y-b.y, a.z-b.z); }
__device__ __forceinline__ F3 crs3(F3 a, F3 b) {
    return mk3(a.y*b.z - a.z*b.y, a.z*b.x - a.x*b.z, a.x*b.y - a.y*b.x);
}
__device__ __forceinline__ float dot3(F3 a, F3 b) { return a.x*b.x + a.y*b.y + a.z*b.z; }
__device__ __forceinline__ F3 ld3(const float* __restrict__ p, int i) {
    return mk3(p[3*i], p[3*i+1], p[3*i+2]);
}

__global__ void k_zero() {
    int i = blockIdx.x * 256 + threadIdx.x;
    ((float4*)g_agg)[i] = make_float4(0.f, 0.f, 0.f, 0.f);
    if (i == 0) { g_ncnt = 0; g_fcnt = 0; }
}

// partition edges by cutoff: dist/11.5 >= 1 -> far (all radial features exactly 0)
__global__ void k_classify(const int* __restrict__ ei, const float* __restrict__ pos) {
    int e = blockIdx.x * 256 + threadIdx.x;
    bool valid = e < NE;
    int ee = valid ? e : NE - 1;
    int j = ei[ee], i = ei[NE + ee];
    F3 d = sub3(ld3(pos, j), ld3(pos, i));
    float dist = sqrtf(dot3(d, d));
    bool far_ = valid && ((dist / 11.5f) >= 1.f);
    bool near_ = valid && !far_;
    int lane = threadIdx.x & 31;
    unsigned bf = __ballot_sync(0xffffffffu, far_);
    unsigned bn = __ballot_sync(0xffffffffu, near_);
    // far group
    if (bf) {
        int src = __ffs(bf) - 1;
        int base = 0;
        if (lane == src) base = atomicAdd(&g_fcnt, __popc(bf));
        base = __shfl_sync(0xffffffffu, base, src);
        if (far_) g_fJI[base + __popc(bf & ((1u << lane) - 1))] = make_int2(j, i);
    }
    if (bn) {
        int src = __ffs(bn) - 1;
        int base = 0;
        if (lane == src) base = atomicAdd(&g_ncnt, __popc(bn));
        base = __shfl_sync(0xffffffffu, base, src);
        if (near_) g_nJI[base + __popc(bn & ((1u << lane) - 1))] = make_int2(j, i);
    }
}

// x[:,0:64] = [onehot(z), bb, sc] @ W_emb + b_emb
__global__ void k_embed(const int* __restrict__ z, const float* __restrict__ bb,
                        const float* __restrict__ sc, const float* __restrict__ W,
                        const float* __restrict__ b) {
    __shared__ float sW[40 * 64];
    __shared__ float sb[64];
    int tid = threadIdx.x;
    for (int idx = tid; idx < 40 * 64; idx += 256) sW[idx] = W[idx];
    if (tid < 64) sb[tid] = b[tid];
    __syncthreads();
    int n = blockIdx.x * 4 + (tid >> 6);
    int c = tid & 63;
    if (n < NN) {
        float acc = sb[c] + sW[z[n] * 64 + c];
        #pragma unroll
        for (int q = 0; q < 6; q++) acc += bb[n * 6 + q] * sW[(26 + q) * 64 + c];
        #pragma unroll
        for (int q = 0; q < 8; q++) acc += sc[n * 8 + q] * sW[(32 + q) * 64 + c];
        g_x[n * HH + c] = acc;
    }
}

// x[:,64:128] = esm @ W_esm + b_esm
__global__ void __launch_bounds__(256) k_esm(const float* __restrict__ esm,
                                             const float* __restrict__ W,
                                             const float* __restrict__ b) {
    __shared__ __align__(16) float As[32][68];
    __shared__ __align__(16) float Bs[32][64];
    int tid = threadIdx.x;
    int m0 = blockIdx.x * 64;
    int ty = tid >> 4, tx = tid & 15;
    float acc[4][4] = {};
    for (int k0 = 0; k0 < 1280; k0 += 32) {
        #pragma unroll
        for (int it = 0; it < 8; it++) {
            int idx = it * 256 + tid;
            int m = idx >> 5, k = idx & 31;
            int row = m0 + m; if (row >= NN) row = NN - 1;
            As[k][m] = esm[row * 1280 + k0 + k];
        }
        #pragma unroll
        for (int it = 0; it < 8; it++) {
            int idx = it * 256 + tid;
            int k = idx >> 6, c = idx & 63;
            Bs[k][c] = W[(k0 + k) * 64 + c];
        }
        __syncthreads();
        #pragma unroll 8
        for (int k = 0; k < 32; k++) {
            float4 av = *(const float4*)&As[k][ty * 4];
            float4 bv = *(const float4*)&Bs[k][tx * 4];
            float ar[4] = {av.x, av.y, av.z, av.w};
            float br[4] = {bv.x, bv.y, bv.z, bv.w};
            #pragma unroll
            for (int mm = 0; mm < 4; mm++)
                #pragma unroll
                for (int cc = 0; cc < 4; cc++) acc[mm][cc] += ar[mm] * br[cc];
        }
        __syncthreads();
    }
    #pragma unroll
    for (int mm = 0; mm < 4; mm++) {
        int row = m0 + ty * 4 + mm;
        if (row < NN) {
            #pragma unroll
            for (int cc = 0; cc < 4; cc++)
                g_x[row * HH + 64 + tx * 4 + cc] = acc[mm][cc] + b[tx * 4 + cc];
        }
    }
}

// [N,128]@[128,128]. EPI0: xm=swish(x@W)  EPI1: xe=x+swish(agg@W)  EPI2: h0=relu(xe@W+b)
template <int EPI>
__global__ void __launch_bounds__(256) k_gemm128(const float* __restrict__ W,
                                                 const float* __restrict__ bias) {
    extern __shared__ float sm[];
    float* Xs = sm;               // 128*68 [k][m]
    float* Ws = sm + 128 * 68;    // 128*128 [k][c]
    int tid = threadIdx.x;
    int m0 = blockIdx.x * 64;
    const float* A = (EPI == 0) ? g_x : (EPI == 1) ? g_agg : g_xm;
    float* O = (EPI == 2) ? g_agg : g_xm;
    for (int idx = tid; idx < 128 * 128; idx += 256) Ws[idx] = W[idx];
    #pragma unroll
    for (int it = 0; it < 32; it++) {
        int idx = it * 256 + tid;
        int m = idx >> 7, k = idx & 127;
        int row = m0 + m; if (row >= NN) row = NN - 1;
        Xs[k * 68 + m] = A[row * HH + k];
    }
    __syncthreads();
    int ty = tid >> 4, tx = tid & 15;
    float acc[4][8] = {};
    #pragma unroll 8
    for (int k = 0; k < 128; k++) {
        float4 av = *(const float4*)&Xs[k * 68 + ty * 4];
        float4 b0 = *(const float4*)&Ws[k * 128 + tx * 8];
        float4 b1 = *(const float4*)&Ws[k * 128 + tx * 8 + 4];
        float ar[4] = {av.x, av.y, av.z, av.w};
        float br[8] = {b0.x, b0.y, b0.z, b0.w, b1.x, b1.y, b1.z, b1.w};
        #pragma unroll
        for (int mm = 0; mm < 4; mm++)
            #pragma unroll
            for (int cc = 0; cc < 8; cc++) acc[mm][cc] += ar[mm] * br[cc];
    }
    #pragma unroll
    for (int mm = 0; mm < 4; mm++) {
        int row = m0 + ty * 4 + mm;
        if (row < NN) {
            #pragma unroll
            for (int cc = 0; cc < 8; cc++) {
                int c = tx * 8 + cc;
                float v;
                if (EPI == 2) v = fmaxf(acc[mm][cc] + bias[c], 0.f);
                else if (EPI == 1) v = g_x[row * HH + c] + swishf(acc[mm][cc]);
                else v = swishf(acc[mm][cc]);
                O[row * HH + c] = v;
            }
        }
    }
}

__device__ __forceinline__ void scatter_msg(const float* acc8, int j, int i, int cg) {
    const float* xr = g_xm + j * HH + cg * 8;
    float* ar = g_agg + i * HH + cg * 8;
    float4 x0 = *(const float4*)xr;
    float4 x1 = *(const float4*)(xr + 4);
    float m0v = swishf(acc8[0]) * x0.x;
    float m1v = swishf(acc8[1]) * x0.y;
    float m2v = swishf(acc8[2]) * x0.z;
    float m3v = swishf(acc8[3]) * x0.w;
    float m4v = swishf(acc8[4]) * x1.x;
    float m5v = swishf(acc8[5]) * x1.y;
    float m6v = swishf(acc8[6]) * x1.z;
    float m7v = swishf(acc8[7]) * x1.w;
    asm volatile("red.global.add.v4.f32 [%0], {%1,%2,%3,%4};"
                 :: "l"(ar), "f"(m0v), "f"(m1v), "f"(m2v), "f"(m3v) : "memory");
    asm volatile("red.global.add.v4.f32 [%0], {%1,%2,%3,%4};"
                 :: "l"(ar + 4), "f"(m4v), "f"(m5v), "f"(m6v), "f"(m7v) : "memory");
}

// near edges (dist < cutoff): full 124-feature path, 64 edges/block
__global__ void __launch_bounds__(256) k_edge_near(const float* __restrict__ pos,
                                                   const float* __restrict__ posn,
                                                   const float* __restrict__ posc,
                                                   const float* __restrict__ We) {
    int cnt = g_ncnt;
    if (blockIdx.x * 64 >= cnt) return;
    extern __shared__ float sm[];
    float* Ws = sm;                          // 124*128
    float* Fs = sm + 124 * 128;              // 124*68 [k][e]
    int* js = (int*)(sm + 124 * 128 + 124 * 68);
    int* is_ = js + 64;
    float* freqs = (float*)(is_ + 64);
    int tid = threadIdx.x;
    for (int idx = tid; idx < 124 * 128; idx += 256) Ws[idx] = We[idx];
    if (tid < 8) {
        float t = (float)(2 * tid) * (float)(-0.5756462732485115);
        freqs[tid] = (float)exp((double)t);
    }
    __syncthreads();
    if (tid < 64) {
        int idx = blockIdx.x * 64 + tid;
        bool valid = idx < cnt;
        int2 ji = g_nJI[valid ? idx : cnt - 1];
        int j = ji.x, i = ji.y;
        js[tid] = valid ? j : -1;
        is_[tid] = i;
        F3 pi_ = ld3(pos, i), pj = ld3(pos, j);
        F3 vji = sub3(pj, pi_);
        float dist = sqrtf(dot3(vji, vji));
        int r0 = (i == 0) ? NN - 1 : i - 1;
        int r1 = (i == NN - 1) ? 0 : i + 1;
        F3 vr0 = sub3(ld3(pos, r0), pi_);
        F3 vr1 = sub3(ld3(pos, r1), pi_);
        float a = dot3(vji, vr0);
        F3 cr = crs3(vji, vr0);
        float b2 = dot3(cr, cr);
        float ct1 = a * rsqrtf(fmaxf(a * a + b2, 1e-30f));
        float ct2 = 2.f * ct1 * ct1 - 1.f;
        F3 p1 = crs3(vr0, vr1), p2 = crs3(vr0, vji);
        float ap = dot3(p1, p2);
        F3 c12 = crs3(p1, p2);
        float bp = dot3(c12, vr0) / (sqrtf(dot3(vr0, vr0)) + 1e-7f);
        float cp1 = ap * rsqrtf(fmaxf(ap * ap + bp * bp, 1e-30f));
        float cp2 = 2.f * cp1 * cp1 - 1.f;
        F3 o1x = sub3(ld3(posn, i), pi_);
        F3 o1z = crs3(o1x, crs3(o1x, sub3(ld3(posc, i), pi_)));
        float o1zl = sqrtf(dot3(o1z, o1z)) + 1e-7f;
        F3 o2x = sub3(ld3(posn, j), pj);
        F3 o2z = crs3(o2x, crs3(o2x, sub3(ld3(posc, j), pj)));
        float o2zl = sqrtf(dot3(o2z, o2z)) + 1e-7f;
        F3 nv = crs3(o1z, o2z);
        float a1 = dot3(o1x, nv);
        float b1 = dot3(crs3(o1x, nv), o1z) / o1zl;
        float cA10 = a1 * rsqrtf(fmaxf(a1 * a1 + b1 * b1, 1e-30f));
        float cA11 = 2.f * cA10 * cA10 - 1.f;
        float a2 = dot3(o1z, o2z);
        float b2v = sqrtf(dot3(nv, nv));
        float cA20 = a2 * rsqrtf(fmaxf(a2 * a2 + b2v * b2v, 1e-30f));
        float cA21 = 2.f * cA20 * cA20 - 1.f;
        float a3 = dot3(nv, o2x);
        float b3 = dot3(crs3(nv, o2x), o2z) / o2zl;
        float cA30 = a3 * rsqrtf(fmaxf(a3 * a3 + b3 * b3, 1e-30f));
        float cA31 = 2.f * cA30 * cA30 - 1.f;
        float u = fminf(dist / 11.5f, 1.f);
        float fc = 0.5f * (cosf(3.14159274f * u) + 1.f);
        float rs = (float)0.41702882811414954 * fc / (dist + 1e-6f);
        float r[6];
        #pragma unroll
        for (int n = 0; n < 6; n++)
            r[n] = rs * sinf((float)(n + 1) * 3.14159274f * u);
        float ct[3] = {1.f, ct1, ct2};
        float cp[3] = {1.f, cp1, cp2};
        #pragma unroll
        for (int n = 0; n < 6; n++)
            #pragma unroll
            for (int l = 0; l < 3; l++) {
                float rl = r[n] * ct[l];
                #pragma unroll
                for (int m = 0; m < 3; m++)
                    Fs[(n * 9 + l * 3 + m) * 68 + tid] = rl * cp[m];
            }
        float cA[3][3] = {{1.f, cA10, cA11}, {1.f, cA20, cA21}, {1.f, cA30, cA31}};
        #pragma unroll
        for (int t = 0; t < 3; t++)
            #pragma unroll
            for (int n = 0; n < 6; n++)
                #pragma unroll
                for (int l = 0; l < 3; l++)
                    Fs[(54 + t * 18 + n * 3 + l) * 68 + tid] = r[n] * cA[t][l];
        float dpe = (float)(j - i);
        #pragma unroll
        for (int kk = 0; kk < 8; kk++) {
            float s, c;
            sincosf(dpe * freqs[kk], &s, &c);
            Fs[(108 + kk) * 68 + tid] = c;
            Fs[(116 + kk) * 68 + tid] = s;
        }
    }
    __syncthreads();
    int eg = tid >> 4, cg = tid & 15;
    float acc[4][8] = {};
    #pragma unroll 4
    for (int k = 0; k < 124; k++) {
        float4 av = *(const float4*)&Fs[k * 68 + eg * 4];
        float4 b0 = *(const float4*)&Ws[k * 128 + cg * 8];
        float4 b1 = *(const float4*)&Ws[k * 128 + cg * 8 + 4];
        float ar[4] = {av.x, av.y, av.z, av.w};
        float br[8] = {b0.x, b0.y, b0.z, b0.w, b1.x, b1.y, b1.z, b1.w};
        #pragma unroll
        for (int mm = 0; mm < 4; mm++)
            #pragma unroll
            for (int cc = 0; cc < 8; cc++) acc[mm][cc] += ar[mm] * br[cc];
    }
    #pragma unroll
    for (int mm = 0; mm < 4; mm++) {
        int el = eg * 4 + mm;
        int j = js[el];
        if (j >= 0) scatter_msg(acc[mm], j, is_[el], cg);
    }
}

// far edges (dist >= cutoff): only 16 positional-embedding features are nonzero
__global__ void __launch_bounds__(256) k_edge_far(const float* __restrict__ We) {
    int cnt = g_fcnt;
    if (blockIdx.x * 64 >= cnt) return;
    __shared__ __align__(16) float Ws[16 * 128];
    __shared__ __align__(16) float Fs[16 * 68];
    __shared__ int js[64], is_[64];
    __shared__ float freqs[8];
    int tid = threadIdx.x;
    for (int idx = tid; idx < 16 * 128; idx += 256) Ws[idx] = We[108 * 128 + idx];
    if (tid < 8) {
        float t = (float)(2 * tid) * (float)(-0.5756462732485115);
        freqs[tid] = (float)exp((double)t);
    }
    __syncthreads();
    if (tid < 64) {
        int idx = blockIdx.x * 64 + tid;
        bool valid = idx < cnt;
        int2 ji = g_fJI[valid ? idx : cnt - 1];
        int j = ji.x, i = ji.y;
        js[tid] = valid ? j : -1;
        is_[tid] = i;
        float dpe = (float)(j - i);
        #pragma unroll
        for (int kk = 0; kk < 8; kk++) {
            float s, c;
            sincosf(dpe * freqs[kk], &s, &c);
            Fs[kk * 68 + tid] = c;
            Fs[(8 + kk) * 68 + tid] = s;
        }
    }
    __syncthreads();
    int eg = tid >> 4, cg = tid & 15;
    float acc[4][8] = {};
    #pragma unroll
    for (int k = 0; k < 16; k++) {
        float4 av = *(const float4*)&Fs[k * 68 + eg * 4];
        float4 b0 = *(const float4*)&Ws[k * 128 + cg * 8];
        float4 b1 = *(const float4*)&Ws[k * 128 + cg * 8 + 4];
        float ar[4] = {av.x, av.y, av.z, av.w};
        float br[8] = {b0.x, b0.y, b0.z, b0.w, b1.x, b1.y, b1.z, b1.w};
        #pragma unroll
        for (int mm = 0; mm < 4; mm++)
            #pragma unroll
            for (int cc = 0; cc < 8; cc++) acc[mm][cc] += ar[mm] * br[cc];
    }
    #pragma unroll
    for (int mm = 0; mm < 4; mm++) {
        int el = eg * 4 + mm;
        int j = js[el];
        if (j >= 0) scatter_msg(acc[mm], j, is_[el], cg);
    }
}

// node head: one warp per node
__global__ void __launch_bounds__(256) k_nodehead(const float* __restrict__ W0,
                                                  const float* __restrict__ b0,
                                                  const float* __restrict__ Wf,
                                                  const float* __restrict__ bf,
                                                  float* __restrict__ out2) {
    __shared__ float sW[4096];
    __shared__ float sb[32], sWf[64], sbf[2];
    int tid = threadIdx.x;
    for (int idx = tid; idx < 4096; idx += 256) sW[idx] = W0[idx];
    if (tid < 32) sb[tid] = b0[tid];
    if (tid < 64) sWf[tid] = Wf[tid];
    if (tid < 2) sbf[tid] = bf[tid];
    __syncthreads();
    int w = tid >> 5, lane = tid & 31;
    int n = blockIdx.x * 8 + w;
    if (n >= NN) return;
    const float* xr = g_x + n * HH;
    float acc = sb[lane];
    #pragma unroll 8
    for (int k = 0; k < 128; k++) acc += xr[k] * sW[k * 32 + lane];
    float xn = fmaxf(acc, 0.f);
    float v0 = xn * sWf[lane * 2], v1 = xn * sWf[lane * 2 + 1];
    #pragma unroll
    for (int off = 16; off > 0; off >>= 1) {
        v0 += __shfl_xor_sync(0xffffffffu, v0, off);
        v1 += __shfl_xor_sync(0xffffffffu, v1, off);
    }
    if (lane == 0) { out2[n * 2] = v0 + sbf[0]; out2[n * 2 + 1] = v1 + sbf[1]; }
}

// final head: out = sigmoid(relu(h0@W_o1+b)@W_of+b)
__global__ void __launch_bounds__(256) k_final(const float* __restrict__ W1,
                                               const float* __restrict__ b1,
                                               const float* __restrict__ Wf,
                                               const float* __restrict__ bf,
                                               float* __restrict__ out) {
    __shared__ float sW[4096];
    __shared__ float sb[32], sWf[32];
    int tid = threadIdx.x;
    for (int idx = tid; idx < 4096; idx += 256) sW[idx] = W1[idx];
    if (tid < 32) { sb[tid] = b1[tid]; sWf[tid] = Wf[tid]; }
    __syncthreads();
    int w = tid >> 5, lane = tid & 31;
    int n = blockIdx.x * 8 + w;
    if (n >= NN) return;
    const float* hr = g_agg + n * HH;
    float acc = sb[lane];
    #pragma unroll 8
    for (int k = 0; k < 128; k++) acc += hr[k] * sW[k * 32 + lane];
    float v = fmaxf(acc, 0.f) * sWf[lane];
    #pragma unroll
    for (int off = 16; off > 0; off >>= 1) v += __shfl_xor_sync(0xffffffffu, v, off);
    if (lane == 0) out[n] = 1.f / (1.f + expf(-(v + bf[0])));
}

extern "C" void kernel_launch(void* const* d_in, const int* in_sizes, int n_in,
                              void* d_out, int out_size) {
    const int* z = (const int*)d_in[0];
    const float* pos = (const float*)d_in[1];
    const float* posn = (const float*)d_in[2];
    const float* posc = (const float*)d_in[3];
    const float* bb = (const float*)d_in[4];
    const float* sc = (const float*)d_in[5];
    const float* esm = (const float*)d_in[6];
    const int* ei = (const int*)d_in[8];
    const float* W_emb = (const float*)d_in[9];
    const float* b_emb = (const float*)d_in[10];
    const float* W_esm = (const float*)d_in[11];
    const float* b_esm = (const float*)d_in[12];
    const float* W_edge = (const float*)d_in[13];
    const float* W_msg = (const float*)d_in[14];
    const float* W_upd = (const float*)d_in[15];
    const float* W_o0 = (const float*)d_in[16];
    const float* b_o0 = (const float*)d_in[17];
    const float* W_o1 = (const float*)d_in[18];
    const float* b_o1 = (const float*)d_in[19];
    const float* W_of = (const float*)d_in[20];
    const float* b_of = (const float*)d_in[21];
    const float* W_n0 = (const float*)d_in[22];
    const float* b_n0 = (const float*)d_in[23];
    const float* W_nf = (const float*)d_in[24];
    const float* b_nf = (const float*)d_in[25];
    float* out = (float*)d_out;

    static bool attr_done = false;
    if (!attr_done) {
        cudaFuncSetAttribute(k_gemm128<0>, cudaFuncAttributeMaxDynamicSharedMemorySize, 100352);
        cudaFuncSetAttribute(k_gemm128<1>, cudaFuncAttributeMaxDynamicSharedMemorySize, 100352);
        cudaFuncSetAttribute(k_gemm128<2>, cudaFuncAttributeMaxDynamicSharedMemorySize, 100352);
        cudaFuncSetAttribute(k_edge_near, cudaFuncAttributeMaxDynamicSharedMemorySize, 97760);
        attr_done = true;
    }

    k_zero<<<6250, 256>>>();
    k_classify<<<3907, 256>>>(ei, pos);
    k_embed<<<12500, 256>>>(z, bb, sc, W_emb, b_emb);
    k_esm<<<782, 256>>>(esm, W_esm, b_esm);
    k_gemm128<0><<<782, 256, 100352>>>(W_msg, nullptr);
    k_edge_near<<<15625, 256, 97760>>>(pos, posn, posc, W_edge);
    k_edge_far<<<15625, 256>>>(W_edge);
    k_gemm128<1><<<782, 256, 100352>>>(W_upd, nullptr);
    k_gemm128<2><<<782, 256, 100352>>>(W_o0, b_o0);
    k_nodehead<<<6250, 256>>>(W_n0, b_n0, W_nf, b_nf, out + NN);
    k_final<<<6250, 256>>>(W_o1, b_o1, W_of, b_of, out);
}

// round 4
// speedup vs baseline: 2.0049x; 1.2605x over previous
#include <cuda_runtime.h>
#include <cuda_bf16.h>
#include <math.h>

#define NN 50000
#define NE 1000000
#define HH 128

__device__ float g_x[NN * HH];    // node features
__device__ float g_xm[NN * HH];   // swish(x@W_msg); later xe
__device__ float g_agg[NN * HH];  // scatter target; later h0
__device__ int g_ncnt, g_fcnt;
__device__ int2 g_nJI[NE];
__device__ int2 g_fJI[NE];

__device__ __forceinline__ float swishf(float v) { return v / (1.f + expf(-v)); }

struct F3 { float x, y, z; };
__device__ __forceinline__ F3 mk3(float a, float b, float c) { F3 r; r.x=a; r.y=b; r.z=c; return r; }
__device__ __forceinline__ F3 sub3(F3 a, F3 b) { return mk3(a.x-b.x, a.y-b.y, a.z-b.z); }
__device__ __forceinline__ F3 crs3(F3 a, F3 b) {
    return mk3(a.y*b.z - a.z*b.y, a.z*b.x - a.x*b.z, a.x*b.y - a.y*b.x);
}
__device__ __forceinline__ float dot3(F3 a, F3 b) { return a.x*b.x + a.y*b.y + a.z*b.z; }
__device__ __forceinline__ F3 ld3(const float* __restrict__ p, int i) {
    return mk3(p[3*i], p[3*i+1], p[3*i+2]);
}
__device__ __forceinline__ unsigned sptr(const void* p) {
    return (unsigned)__cvta_generic_to_shared(p);
}

#define LDSM4(r0,r1,r2,r3,addr) \
    asm volatile("ldmatrix.sync.aligned.m8n8.x4.shared.b16 {%0,%1,%2,%3},[%4];" \
                 : "=r"(r0),"=r"(r1),"=r"(r2),"=r"(r3) : "r"(addr))
#define LDSM4T(r0,r1,r2,r3,addr) \
    asm volatile("ldmatrix.sync.aligned.m8n8.x4.trans.shared.b16 {%0,%1,%2,%3},[%4];" \
                 : "=r"(r0),"=r"(r1),"=r"(r2),"=r"(r3) : "r"(addr))
#define MMA16816(d,a0,a1,a2,a3,b0,b1) \
    asm volatile("mma.sync.aligned.m16n8k16.row.col.f32.bf16.bf16.f32 " \
                 "{%0,%1,%2,%3},{%4,%5,%6,%7},{%8,%9},{%0,%1,%2,%3};" \
                 : "+f"(d[0]),"+f"(d[1]),"+f"(d[2]),"+f"(d[3]) \
                 : "r"(a0),"r"(a1),"r"(a2),"r"(a3),"r"(b0),"r"(b1))

__global__ void k_zero() {
    int i = blockIdx.x * 256 + threadIdx.x;
    ((float4*)g_agg)[i] = make_float4(0.f, 0.f, 0.f, 0.f);
    if (i == 0) { g_ncnt = 0; g_fcnt = 0; }
}

// partition edges by cutoff: dist/11.5 >= 1 -> far (radial features exactly 0)
__global__ void k_classify(const int* __restrict__ ei, const float* __restrict__ pos) {
    int e = blockIdx.x * 256 + threadIdx.x;
    bool valid = e < NE;
    int ee = valid ? e : NE - 1;
    int j = ei[ee], i = ei[NE + ee];
    F3 d = sub3(ld3(pos, j), ld3(pos, i));
    float dist = sqrtf(dot3(d, d));
    bool far_ = valid && ((dist / 11.5f) >= 1.f);
    bool near_ = valid && !far_;
    int lane = threadIdx.x & 31;
    unsigned bf = __ballot_sync(0xffffffffu, far_);
    unsigned bn = __ballot_sync(0xffffffffu, near_);
    if (bf) {
        int src = __ffs(bf) - 1;
        int base = 0;
        if (lane == src) base = atomicAdd(&g_fcnt, __popc(bf));
        base = __shfl_sync(0xffffffffu, base, src);
        if (far_) g_fJI[base + __popc(bf & ((1u << lane) - 1))] = make_int2(j, i);
    }
    if (bn) {
        int src = __ffs(bn) - 1;
        int base = 0;
        if (lane == src) base = atomicAdd(&g_ncnt, __popc(bn));
        base = __shfl_sync(0xffffffffu, base, src);
        if (near_) g_nJI[base + __popc(bn & ((1u << lane) - 1))] = make_int2(j, i);
    }
}

// x[:,0:64] = [onehot(z), bb, sc] @ W_emb + b_emb
__global__ void k_embed(const int* __restrict__ z, const float* __restrict__ bb,
                        const float* __restrict__ sc, const float* __restrict__ W,
                        const float* __restrict__ b) {
    __shared__ float sW[40 * 64];
    __shared__ float sb[64];
    int tid = threadIdx.x;
    for (int idx = tid; idx < 40 * 64; idx += 256) sW[idx] = W[idx];
    if (tid < 64) sb[tid] = b[tid];
    __syncthreads();
    int n = blockIdx.x * 4 + (tid >> 6);
    int c = tid & 63;
    if (n < NN) {
        float acc = sb[c] + sW[z[n] * 64 + c];
        #pragma unroll
        for (int q = 0; q < 6; q++) acc += bb[n * 6 + q] * sW[(26 + q) * 64 + c];
        #pragma unroll
        for (int q = 0; q < 8; q++) acc += sc[n * 8 + q] * sW[(32 + q) * 64 + c];
        g_x[n * HH + c] = acc;
    }
}

// ---- tensor-core esm GEMM: x[:,64:128] = esm @ W_esm + b, split-bf16 3-mma ----
// block tile M=128, N=64, KC=32. 8 warps: warp_m = wid&3 (32 rows), warp_n = wid>>2 (32 cols).
__global__ void __launch_bounds__(256) k_esm_tc(const float* __restrict__ esm,
                                                const float* __restrict__ W,
                                                const float* __restrict__ b) {
    __shared__ __nv_bfloat16 AsH[128 * 40];  // pitch 40 bf16 = 80B (conflict-free LDSM)
    __shared__ __nv_bfloat16 AsL[128 * 40];
    __shared__ __nv_bfloat16 BsH[32 * 72];   // pitch 72 bf16 = 144B
    __shared__ __nv_bfloat16 BsL[32 * 72];
    int tid = threadIdx.x;
    int m0 = blockIdx.x * 128;
    int wid = tid >> 5, lane = tid & 31;
    int warp_m = wid & 3, warp_n = wid >> 2;

    int arow = tid >> 1, ahalf = tid & 1;       // A: 128 rows x 32 k, 16 k per thread
    int grow = m0 + arow; if (grow >= NN) grow = NN - 1;
    const float* aptr = esm + (size_t)grow * 1280 + ahalf * 16;
    int brow = tid >> 3, bcol = (tid & 7) * 8;  // B: 32 k x 64 n, 8 n per thread
    const float* bptr = W + brow * 64 + bcol;

    float acc[2][4][4];
    #pragma unroll
    for (int a_ = 0; a_ < 2; a_++)
        #pragma unroll
        for (int b_ = 0; b_ < 4; b_++)
            #pragma unroll
            for (int q = 0; q < 4; q++) acc[a_][b_][q] = 0.f;

    float4 ra[4]; float4 rb[2];
    #pragma unroll
    for (int q = 0; q < 4; q++) ra[q] = *(const float4*)(aptr + q * 4);
    rb[0] = *(const float4*)bptr; rb[1] = *(const float4*)(bptr + 4);

    // ldmatrix lane addressing (constant across chunks)
    int a_r = (lane & 7) + ((lane >> 3) & 1) * 8;   // row within 16
    int a_c = (lane >> 4) * 8;                      // k element offset within 16
    int b_k = (lane & 7) + ((lane >> 3) & 1) * 8;   // k within 16
    int b_n = (lane >> 4) * 8;                      // n offset within 16

    for (int c = 0; c < 40; c++) {
        // convert prefetched regs -> smem (hi/lo split)
        {
            float av[16] = {ra[0].x, ra[0].y, ra[0].z, ra[0].w,
                            ra[1].x, ra[1].y, ra[1].z, ra[1].w,
                            ra[2].x, ra[2].y, ra[2].z, ra[2].w,
                            ra[3].x, ra[3].y, ra[3].z, ra[3].w};
            __nv_bfloat16* dH = AsH + arow * 40 + ahalf * 16;
            __nv_bfloat16* dL = AsL + arow * 40 + ahalf * 16;
            #pragma unroll
            for (int q = 0; q < 16; q++) {
                float x = av[q];
                __nv_bfloat16 h = __float2bfloat16_rn(x);
                dH[q] = h;
                dL[q] = __float2bfloat16_rn(x - __bfloat162float(h));
            }
            float bv[8] = {rb[0].x, rb[0].y, rb[0].z, rb[0].w,
                           rb[1].x, rb[1].y, rb[1].z, rb[1].w};
            __nv_bfloat16* eH = BsH + brow * 72 + bcol;
            __nv_bfloat16* eL = BsL + brow * 72 + bcol;
            #pragma unroll
            for (int q = 0; q < 8; q++) {
                float x = bv[q];
                __nv_bfloat16 h = __float2bfloat16_rn(x);
                eH[q] = h;
                eL[q] = __float2bfloat16_rn(x - __bfloat162float(h));
            }
        }
        __syncthreads();
        if (c < 39) {  // prefetch next chunk (latency hidden behind mma)
            aptr += 32; bptr += 32 * 64;
            #pragma unroll
            for (int q = 0; q < 4; q++) ra[q] = *(const float4*)(aptr + q * 4);
            rb[0] = *(const float4*)bptr; rb[1] = *(const float4*)(bptr + 4);
        }
        #pragma unroll
        for (int ks = 0; ks < 2; ks++) {
            unsigned ah[2][4], al[2][4], bh[2][4], bl[2][4];
            #pragma unroll
            for (int mt = 0; mt < 2; mt++) {
                int row = warp_m * 32 + mt * 16 + a_r;
                int col = ks * 16 + a_c;
                unsigned pH = sptr(AsH + row * 40 + col);
                unsigned pL = sptr(AsL + row * 40 + col);
                LDSM4(ah[mt][0], ah[mt][1], ah[mt][2], ah[mt][3], pH);
                LDSM4(al[mt][0], al[mt][1], al[mt][2], al[mt][3], pL);
            }
            #pragma unroll
            for (int g = 0; g < 2; g++) {
                int kk = ks * 16 + b_k;
                int nn = warp_n * 32 + g * 16 + b_n;
                unsigned pH = sptr(BsH + kk * 72 + nn);
                unsigned pL = sptr(BsL + kk * 72 + nn);
                LDSM4T(bh[g][0], bh[g][1], bh[g][2], bh[g][3], pH);
                LDSM4T(bl[g][0], bl[g][1], bl[g][2], bl[g][3], pL);
            }
            #pragma unroll
            for (int mt = 0; mt < 2; mt++)
                #pragma unroll
                for (int nt = 0; nt < 4; nt++) {
                    int g = nt >> 1, h = (nt & 1) * 2;
                    MMA16816(acc[mt][nt], ah[mt][0], ah[mt][1], ah[mt][2], ah[mt][3],
                             bh[g][h], bh[g][h + 1]);
                    MMA16816(acc[mt][nt], ah[mt][0], ah[mt][1], ah[mt][2], ah[mt][3],
                             bl[g][h], bl[g][h + 1]);
                    MMA16816(acc[mt][nt], al[mt][0], al[mt][1], al[mt][2], al[mt][3],
                             bh[g][h], bh[g][h + 1]);
                }
        }
        __syncthreads();
    }
    // epilogue
    #pragma unroll
    for (int mt = 0; mt < 2; mt++)
        #pragma unroll
        for (int nt = 0; nt < 4; nt++) {
            int row = m0 + warp_m * 32 + mt * 16 + (lane >> 2);
            int col = warp_n * 32 + nt * 8 + (lane & 3) * 2;
            if (row < NN) {
                g_x[row * HH + 64 + col] = acc[mt][nt][0] + b[col];
                g_x[row * HH + 64 + col + 1] = acc[mt][nt][1] + b[col + 1];
            }
            if (row + 8 < NN) {
                g_x[(row + 8) * HH + 64 + col] = acc[mt][nt][2] + b[col];
                g_x[(row + 8) * HH + 64 + col + 1] = acc[mt][nt][3] + b[col + 1];
            }
        }
}

// [N,128]@[128,128]. EPI0: xm=swish(x@W)  EPI1: xe=x+swish(agg@W)  EPI2: h0=relu(xe@W+b)
template <int EPI>
__global__ void __launch_bounds__(256) k_gemm128(const float* __restrict__ W,
                                                 const float* __restrict__ bias) {
    extern __shared__ float sm[];
    float* Xs = sm;               // 128*68 [k][m]
    float* Ws = sm + 128 * 68;    // 128*128 [k][c]
    int tid = threadIdx.x;
    int m0 = blockIdx.x * 64;
    const float* A = (EPI == 0) ? g_x : (EPI == 1) ? g_agg : g_xm;
    float* O = (EPI == 2) ? g_agg : g_xm;
    for (int idx = tid; idx < 128 * 128; idx += 256) Ws[idx] = W[idx];
    #pragma unroll
    for (int it = 0; it < 32; it++) {
        int idx = it * 256 + tid;
        int m = idx >> 7, k = idx & 127;
        int row = m0 + m; if (row >= NN) row = NN - 1;
        Xs[k * 68 + m] = A[row * HH + k];
    }
    __syncthreads();
    int ty = tid >> 4, tx = tid & 15;
    float acc[4][8] = {};
    #pragma unroll 8
    for (int k = 0; k < 128; k++) {
        float4 av = *(const float4*)&Xs[k * 68 + ty * 4];
        float4 b0 = *(const float4*)&Ws[k * 128 + tx * 8];
        float4 b1 = *(const float4*)&Ws[k * 128 + tx * 8 + 4];
        float ar[4] = {av.x, av.y, av.z, av.w};
        float br[8] = {b0.x, b0.y, b0.z, b0.w, b1.x, b1.y, b1.z, b1.w};
        #pragma unroll
        for (int mm = 0; mm < 4; mm++)
            #pragma unroll
            for (int cc = 0; cc < 8; cc++) acc[mm][cc] += ar[mm] * br[cc];
    }
    #pragma unroll
    for (int mm = 0; mm < 4; mm++) {
        int row = m0 + ty * 4 + mm;
        if (row < NN) {
            #pragma unroll
            for (int cc = 0; cc < 8; cc++) {
                int c = tx * 8 + cc;
                float v;
                if (EPI == 2) v = fmaxf(acc[mm][cc] + bias[c], 0.f);
                else if (EPI == 1) v = g_x[row * HH + c] + swishf(acc[mm][cc]);
                else v = swishf(acc[mm][cc]);
                O[row * HH + c] = v;
            }
        }
    }
}

__device__ __forceinline__ void scatter_msg(const float* acc8, int j, int i, int cg) {
    const float* xr = g_xm + j * HH + cg * 8;
    float* ar = g_agg + i * HH + cg * 8;
    float4 x0 = *(const float4*)xr;
    float4 x1 = *(const float4*)(xr + 4);
    float m0v = swishf(acc8[0]) * x0.x;
    float m1v = swishf(acc8[1]) * x0.y;
    float m2v = swishf(acc8[2]) * x0.z;
    float m3v = swishf(acc8[3]) * x0.w;
    float m4v = swishf(acc8[4]) * x1.x;
    float m5v = swishf(acc8[5]) * x1.y;
    float m6v = swishf(acc8[6]) * x1.z;
    float m7v = swishf(acc8[7]) * x1.w;
    asm volatile("red.global.add.v4.f32 [%0], {%1,%2,%3,%4};"
                 :: "l"(ar), "f"(m0v), "f"(m1v), "f"(m2v), "f"(m3v) : "memory");
    asm volatile("red.global.add.v4.f32 [%0], {%1,%2,%3,%4};"
                 :: "l"(ar + 4), "f"(m4v), "f"(m5v), "f"(m6v), "f"(m7v) : "memory");
}

// near edges (dist < cutoff): full 124-feature path, 64 edges/block
__global__ void __launch_bounds__(256) k_edge_near(const float* __restrict__ pos,
                                                   const float* __restrict__ posn,
                                                   const float* __restrict__ posc,
                                                   const float* __restrict__ We) {
    int cnt = g_ncnt;
    if (blockIdx.x * 64 >= cnt) return;
    extern __shared__ float sm[];
    float* Ws = sm;                          // 124*128
    float* Fs = sm + 124 * 128;              // 124*68 [k][e]
    int* js = (int*)(sm + 124 * 128 + 124 * 68);
    int* is_ = js + 64;
    float* freqs = (float*)(is_ + 64);
    int tid = threadIdx.x;
    for (int idx = tid; idx < 124 * 128; idx += 256) Ws[idx] = We[idx];
    if (tid < 8) {
        float t = (float)(2 * tid) * (float)(-0.5756462732485115);
        freqs[tid] = (float)exp((double)t);
    }
    __syncthreads();
    if (tid < 64) {
        int idx = blockIdx.x * 64 + tid;
        bool valid = idx < cnt;
        int2 ji = g_nJI[valid ? idx : cnt - 1];
        int j = ji.x, i = ji.y;
        js[tid] = valid ? j : -1;
        is_[tid] = i;
        F3 pi_ = ld3(pos, i), pj = ld3(pos, j);
        F3 vji = sub3(pj, pi_);
        float dist = sqrtf(dot3(vji, vji));
        int r0 = (i == 0) ? NN - 1 : i - 1;
        int r1 = (i == NN - 1) ? 0 : i + 1;
        F3 vr0 = sub3(ld3(pos, r0), pi_);
        F3 vr1 = sub3(ld3(pos, r1), pi_);
        float a = dot3(vji, vr0);
        F3 cr = crs3(vji, vr0);
        float b2 = dot3(cr, cr);
        float ct1 = a * rsqrtf(fmaxf(a * a + b2, 1e-30f));
        float ct2 = 2.f * ct1 * ct1 - 1.f;
        F3 p1 = crs3(vr0, vr1), p2 = crs3(vr0, vji);
        float ap = dot3(p1, p2);
        F3 c12 = crs3(p1, p2);
        float bp = dot3(c12, vr0) / (sqrtf(dot3(vr0, vr0)) + 1e-7f);
        float cp1 = ap * rsqrtf(fmaxf(ap * ap + bp * bp, 1e-30f));
        float cp2 = 2.f * cp1 * cp1 - 1.f;
        F3 o1x = sub3(ld3(posn, i), pi_);
        F3 o1z = crs3(o1x, crs3(o1x, sub3(ld3(posc, i), pi_)));
        float o1zl = sqrtf(dot3(o1z, o1z)) + 1e-7f;
        F3 o2x = sub3(ld3(posn, j), pj);
        F3 o2z = crs3(o2x, crs3(o2x, sub3(ld3(posc, j), pj)));
        float o2zl = sqrtf(dot3(o2z, o2z)) + 1e-7f;
        F3 nv = crs3(o1z, o2z);
        float a1 = dot3(o1x, nv);
        float b1 = dot3(crs3(o1x, nv), o1z) / o1zl;
        float cA10 = a1 * rsqrtf(fmaxf(a1 * a1 + b1 * b1, 1e-30f));
        float cA11 = 2.f * cA10 * cA10 - 1.f;
        float a2 = dot3(o1z, o2z);
        float b2v = sqrtf(dot3(nv, nv));
        float cA20 = a2 * rsqrtf(fmaxf(a2 * a2 + b2v * b2v, 1e-30f));
        float cA21 = 2.f * cA20 * cA20 - 1.f;
        float a3 = dot3(nv, o2x);
        float b3 = dot3(crs3(nv, o2x), o2z) / o2zl;
        float cA30 = a3 * rsqrtf(fmaxf(a3 * a3 + b3 * b3, 1e-30f));
        float cA31 = 2.f * cA30 * cA30 - 1.f;
        float u = fminf(dist / 11.5f, 1.f);
        float fc = 0.5f * (cosf(3.14159274f * u) + 1.f);
        float rs = (float)0.41702882811414954 * fc / (dist + 1e-6f);
        float r[6];
        #pragma unroll
        for (int n = 0; n < 6; n++)
            r[n] = rs * sinf((float)(n + 1) * 3.14159274f * u);
        float ct[3] = {1.f, ct1, ct2};
        float cp[3] = {1.f, cp1, cp2};
        #pragma unroll
        for (int n = 0; n < 6; n++)
            #pragma unroll
            for (int l = 0; l < 3; l++) {
                float rl = r[n] * ct[l];
                #pragma unroll
                for (int m = 0; m < 3; m++)
                    Fs[(n * 9 + l * 3 + m) * 68 + tid] = rl * cp[m];
            }
        float cA[3][3] = {{1.f, cA10, cA11}, {1.f, cA20, cA21}, {1.f, cA30, cA31}};
        #pragma unroll
        for (int t = 0; t < 3; t++)
            #pragma unroll
            for (int n = 0; n < 6; n++)
                #pragma unroll
                for (int l = 0; l < 3; l++)
                    Fs[(54 + t * 18 + n * 3 + l) * 68 + tid] = r[n] * cA[t][l];
        float dpe = (float)(j - i);
        #pragma unroll
        for (int kk = 0; kk < 8; kk++) {
            float s, c;
            sincosf(dpe * freqs[kk], &s, &c);
            Fs[(108 + kk) * 68 + tid] = c;
            Fs[(116 + kk) * 68 + tid] = s;
        }
    }
    __syncthreads();
    int eg = tid >> 4, cg = tid & 15;
    float acc[4][8] = {};
    #pragma unroll 4
    for (int k = 0; k < 124; k++) {
        float4 av = *(const float4*)&Fs[k * 68 + eg * 4];
        float4 b0 = *(const float4*)&Ws[k * 128 + cg * 8];
        float4 b1 = *(const float4*)&Ws[k * 128 + cg * 8 + 4];
        float ar[4] = {av.x, av.y, av.z, av.w};
        float br[8] = {b0.x, b0.y, b0.z, b0.w, b1.x, b1.y, b1.z, b1.w};
        #pragma unroll
        for (int mm = 0; mm < 4; mm++)
            #pragma unroll
            for (int cc = 0; cc < 8; cc++) acc[mm][cc] += ar[mm] * br[cc];
    }
    #pragma unroll
    for (int mm = 0; mm < 4; mm++) {
        int el = eg * 4 + mm;
        int j = js[el];
        if (j >= 0) scatter_msg(acc[mm], j, is_[el], cg);
    }
}

// far edges (dist >= cutoff): only 16 positional-embedding features nonzero
__global__ void __launch_bounds__(256) k_edge_far(const float* __restrict__ We) {
    int cnt = g_fcnt;
    if (blockIdx.x * 64 >= cnt) return;
    __shared__ __align__(16) float Ws[16 * 128];
    __shared__ __align__(16) float Fs[16 * 68];
    __shared__ int js[64], is_[64];
    __shared__ float freqs[8];
    int tid = threadIdx.x;
    for (int idx = tid; idx < 16 * 128; idx += 256) Ws[idx] = We[108 * 128 + idx];
    if (tid < 8) {
        float t = (float)(2 * tid) * (float)(-0.5756462732485115);
        freqs[tid] = (float)exp((double)t);
    }
    __syncthreads();
    if (tid < 64) {
        int idx = blockIdx.x * 64 + tid;
        bool valid = idx < cnt;
        int2 ji = g_fJI[valid ? idx : cnt - 1];
        int j = ji.x, i = ji.y;
        js[tid] = valid ? j : -1;
        is_[tid] = i;
        float dpe = (float)(j - i);
        #pragma unroll
        for (int kk = 0; kk < 8; kk++) {
            float s, c;
            sincosf(dpe * freqs[kk], &s, &c);
            Fs[kk * 68 + tid] = c;
            Fs[(8 + kk) * 68 + tid] = s;
        }
    }
    __syncthreads();
    int eg = tid >> 4, cg = tid & 15;
    float acc[4][8] = {};
    #pragma unroll
    for (int k = 0; k < 16; k++) {
        float4 av = *(const float4*)&Fs[k * 68 + eg * 4];
        float4 b0 = *(const float4*)&Ws[k * 128 + cg * 8];
        float4 b1 = *(const float4*)&Ws[k * 128 + cg * 8 + 4];
        float ar[4] = {av.x, av.y, av.z, av.w};
        float br[8] = {b0.x, b0.y, b0.z, b0.w, b1.x, b1.y, b1.z, b1.w};
        #pragma unroll
        for (int mm = 0; mm < 4; mm++)
            #pragma unroll
            for (int cc = 0; cc < 8; cc++) acc[mm][cc] += ar[mm] * br[cc];
    }
    #pragma unroll
    for (int mm = 0; mm < 4; mm++) {
        int el = eg * 4 + mm;
        int j = js[el];
        if (j >= 0) scatter_msg(acc[mm], j, is_[el], cg);
    }
}

// node head: one warp per node
__global__ void __launch_bounds__(256) k_nodehead(const float* __restrict__ W0,
                                                  const float* __restrict__ b0,
                                                  const float* __restrict__ Wf,
                                                  const float* __restrict__ bf,
                                                  float* __restrict__ out2) {
    __shared__ float sW[4096];
    __shared__ float sb[32], sWf[64], sbf[2];
    int tid = threadIdx.x;
    for (int idx = tid; idx < 4096; idx += 256) sW[idx] = W0[idx];
    if (tid < 32) sb[tid] = b0[tid];
    if (tid < 64) sWf[tid] = Wf[tid];
    if (tid < 2) sbf[tid] = bf[tid];
    __syncthreads();
    int w = tid >> 5, lane = tid & 31;
    int n = blockIdx.x * 8 + w;
    if (n >= NN) return;
    const float* xr = g_x + n * HH;
    float acc = sb[lane];
    #pragma unroll 8
    for (int k = 0; k < 128; k++) acc += xr[k] * sW[k * 32 + lane];
    float xn = fmaxf(acc, 0.f);
    float v0 = xn * sWf[lane * 2], v1 = xn * sWf[lane * 2 + 1];
    #pragma unroll
    for (int off = 16; off > 0; off >>= 1) {
        v0 += __shfl_xor_sync(0xffffffffu, v0, off);
        v1 += __shfl_xor_sync(0xffffffffu, v1, off);
    }
    if (lane == 0) { out2[n * 2] = v0 + sbf[0]; out2[n * 2 + 1] = v1 + sbf[1]; }
}

// final head: out = sigmoid(relu(h0@W_o1+b)@W_of+b)
__global__ void __launch_bounds__(256) k_final(const float* __restrict__ W1,
                                               const float* __restrict__ b1,
                                               const float* __restrict__ Wf,
                                               const float* __restrict__ bf,
                                               float* __restrict__ out) {
    __shared__ float sW[4096];
    __shared__ float sb[32], sWf[32];
    int tid = threadIdx.x;
    for (int idx = tid; idx < 4096; idx += 256) sW[idx] = W1[idx];
    if (tid < 32) { sb[tid] = b1[tid]; sWf[tid] = Wf[tid]; }
    __syncthreads();
    int w = tid >> 5, lane = tid & 31;
    int n = blockIdx.x * 8 + w;
    if (n >= NN) return;
    const float* hr = g_agg + n * HH;
    float acc = sb[lane];
    #pragma unroll 8
    for (int k = 0; k < 128; k++) acc += hr[k] * sW[k * 32 + lane];
    float v = fmaxf(acc, 0.f) * sWf[lane];
    #pragma unroll
    for (int off = 16; off > 0; off >>= 1) v += __shfl_xor_sync(0xffffffffu, v, off);
    if (lane == 0) out[n] = 1.f / (1.f + expf(-(v + bf[0])));
}

extern "C" void kernel_launch(void* const* d_in, const int* in_sizes, int n_in,
                              void* d_out, int out_size) {
    const int* z = (const int*)d_in[0];
    const float* pos = (const float*)d_in[1];
    const float* posn = (const float*)d_in[2];
    const float* posc = (const float*)d_in[3];
    const float* bb = (const float*)d_in[4];
    const float* sc = (const float*)d_in[5];
    const float* esm = (const float*)d_in[6];
    const int* ei = (const int*)d_in[8];
    const float* W_emb = (const float*)d_in[9];
    const float* b_emb = (const float*)d_in[10];
    const float* W_esm = (const float*)d_in[11];
    const float* b_esm = (const float*)d_in[12];
    const float* W_edge = (const float*)d_in[13];
    const float* W_msg = (const float*)d_in[14];
    const float* W_upd = (const float*)d_in[15];
    const float* W_o0 = (const float*)d_in[16];
    const float* b_o0 = (const float*)d_in[17];
    const float* W_o1 = (const float*)d_in[18];
    const float* b_o1 = (const float*)d_in[19];
    const float* W_of = (const float*)d_in[20];
    const float* b_of = (const float*)d_in[21];
    const float* W_n0 = (const float*)d_in[22];
    const float* b_n0 = (const float*)d_in[23];
    const float* W_nf = (const float*)d_in[24];
    const float* b_nf = (const float*)d_in[25];
    float* out = (float*)d_out;

    static bool attr_done = false;
    if (!attr_done) {
        cudaFuncSetAttribute(k_gemm128<0>, cudaFuncAttributeMaxDynamicSharedMemorySize, 100352);
        cudaFuncSetAttribute(k_gemm128<1>, cudaFuncAttributeMaxDynamicSharedMemorySize, 100352);
        cudaFuncSetAttribute(k_gemm128<2>, cudaFuncAttributeMaxDynamicSharedMemorySize, 100352);
        cudaFuncSetAttribute(k_edge_near, cudaFuncAttributeMaxDynamicSharedMemorySize, 97760);
        attr_done = true;
    }

    k_zero<<<6250, 256>>>();
    k_classify<<<3907, 256>>>(ei, pos);
    k_embed<<<12500, 256>>>(z, bb, sc, W_emb, b_emb);
    k_esm_tc<<<391, 256>>>(esm, W_esm, b_esm);
    k_gemm128<0><<<782, 256, 100352>>>(W_msg, nullptr);
    k_edge_near<<<15625, 256, 97760>>>(pos, posn, posc, W_edge);
    k_edge_far<<<15625, 256>>>(W_edge);
    k_gemm128<1><<<782, 256, 100352>>>(W_upd, nullptr);
    k_gemm128<2><<<782, 256, 100352>>>(W_o0, b_o0);
    k_nodehead<<<6250, 256>>>(W_n0, b_n0, W_nf, b_nf, out + NN);
    k_final<<<6250, 256>>>(W_o1, b_o1, W_of, b_of, out);
}

// round 5
// speedup vs baseline: 2.4982x; 1.2460x over previous
#include <cuda_runtime.h>
#include <cuda_bf16.h>
#include <math.h>

#define NN 50000
#define NE 1000000
#define HH 128

__device__ float g_x[NN * HH];    // node features
__device__ float g_xm[NN * HH];   // swish(x@W_msg); later xe
__device__ float g_agg[NN * HH];  // scatter target; later h0
__device__ int g_ncnt, g_fcnt;
__device__ int2 g_nJI[NE];
__device__ int2 g_fJI[NE];

__device__ __forceinline__ float swishf(float v) { return v / (1.f + expf(-v)); }

struct F3 { float x, y, z; };
__device__ __forceinline__ F3 mk3(float a, float b, float c) { F3 r; r.x=a; r.y=b; r.z=c; return r; }
__device__ __forceinline__ F3 sub3(F3 a, F3 b) { return mk3(a.x-b.x, a.y-b.y, a.z-b.z); }
__device__ __forceinline__ F3 crs3(F3 a, F3 b) {
    return mk3(a.y*b.z - a.z*b.y, a.z*b.x - a.x*b.z, a.x*b.y - a.y*b.x);
}
__device__ __forceinline__ float dot3(F3 a, F3 b) { return a.x*b.x + a.y*b.y + a.z*b.z; }
__device__ __forceinline__ F3 ld3(const float* __restrict__ p, int i) {
    return mk3(p[3*i], p[3*i+1], p[3*i+2]);
}
__device__ __forceinline__ unsigned sptr(const void* p) {
    return (unsigned)__cvta_generic_to_shared(p);
}
__device__ __forceinline__ void split2(float x0, float x1, __nv_bfloat162& h, __nv_bfloat162& l) {
    __nv_bfloat16 h0 = __float2bfloat16_rn(x0);
    __nv_bfloat16 h1 = __float2bfloat16_rn(x1);
    h = __halves2bfloat162(h0, h1);
    l = __halves2bfloat162(__float2bfloat16_rn(x0 - __bfloat162float(h0)),
                           __float2bfloat16_rn(x1 - __bfloat162float(h1)));
}
__device__ __forceinline__ void split1(float x, __nv_bfloat16* pH, __nv_bfloat16* pL) {
    __nv_bfloat16 h = __float2bfloat16_rn(x);
    *pH = h;
    *pL = __float2bfloat16_rn(x - __bfloat162float(h));
}

#define LDSM4(r0,r1,r2,r3,addr) \
    asm volatile("ldmatrix.sync.aligned.m8n8.x4.shared.b16 {%0,%1,%2,%3},[%4];" \
                 : "=r"(r0),"=r"(r1),"=r"(r2),"=r"(r3) : "r"(addr))
#define LDSM4T(r0,r1,r2,r3,addr) \
    asm volatile("ldmatrix.sync.aligned.m8n8.x4.trans.shared.b16 {%0,%1,%2,%3},[%4];" \
                 : "=r"(r0),"=r"(r1),"=r"(r2),"=r"(r3) : "r"(addr))
#define MMA16816(d,a0,a1,a2,a3,b0,b1) \
    asm volatile("mma.sync.aligned.m16n8k16.row.col.f32.bf16.bf16.f32 " \
                 "{%0,%1,%2,%3},{%4,%5,%6,%7},{%8,%9},{%0,%1,%2,%3};" \
                 : "+f"(d[0]),"+f"(d[1]),"+f"(d[2]),"+f"(d[3]) \
                 : "r"(a0),"r"(a1),"r"(a2),"r"(a3),"r"(b0),"r"(b1))

__global__ void k_zero() {
    int i = blockIdx.x * 256 + threadIdx.x;
    ((float4*)g_agg)[i] = make_float4(0.f, 0.f, 0.f, 0.f);
    if (i == 0) { g_ncnt = 0; g_fcnt = 0; }
}

// partition edges by cutoff: dist/11.5 >= 1 -> far (radial features exactly 0)
__global__ void k_classify(const int* __restrict__ ei, const float* __restrict__ pos) {
    int e = blockIdx.x * 256 + threadIdx.x;
    bool valid = e < NE;
    int ee = valid ? e : NE - 1;
    int j = ei[ee], i = ei[NE + ee];
    F3 d = sub3(ld3(pos, j), ld3(pos, i));
    float dist = sqrtf(dot3(d, d));
    bool far_ = valid && ((dist / 11.5f) >= 1.f);
    bool near_ = valid && !far_;
    int lane = threadIdx.x & 31;
    unsigned bf = __ballot_sync(0xffffffffu, far_);
    unsigned bn = __ballot_sync(0xffffffffu, near_);
    if (bf) {
        int src = __ffs(bf) - 1;
        int base = 0;
        if (lane == src) base = atomicAdd(&g_fcnt, __popc(bf));
        base = __shfl_sync(0xffffffffu, base, src);
        if (far_) g_fJI[base + __popc(bf & ((1u << lane) - 1))] = make_int2(j, i);
    }
    if (bn) {
        int src = __ffs(bn) - 1;
        int base = 0;
        if (lane == src) base = atomicAdd(&g_ncnt, __popc(bn));
        base = __shfl_sync(0xffffffffu, base, src);
        if (near_) g_nJI[base + __popc(bn & ((1u << lane) - 1))] = make_int2(j, i);
    }
}

// x[:,0:64] = [onehot(z), bb, sc] @ W_emb + b_emb ; 32 nodes/block
__global__ void __launch_bounds__(256) k_embed(const int* __restrict__ z,
                                               const float* __restrict__ bb,
                                               const float* __restrict__ sc,
                                               const float* __restrict__ W,
                                               const float* __restrict__ b) {
    __shared__ float sW[40 * 64];
    __shared__ float sb[64];
    int tid = threadIdx.x;
    for (int idx = tid; idx < 40 * 64; idx += 256) sW[idx] = W[idx];
    if (tid < 64) sb[tid] = b[tid];
    __syncthreads();
    int node = blockIdx.x * 32 + (tid >> 3);
    int c0 = (tid & 7) * 8;
    if (node < NN) {
        float acc[8];
        int zz = z[node];
        #pragma unroll
        for (int cc = 0; cc < 8; cc++) acc[cc] = sb[c0 + cc] + sW[zz * 64 + c0 + cc];
        #pragma unroll
        for (int q = 0; q < 6; q++) {
            float v = bb[node * 6 + q];
            #pragma unroll
            for (int cc = 0; cc < 8; cc++) acc[cc] += v * sW[(26 + q) * 64 + c0 + cc];
        }
        #pragma unroll
        for (int q = 0; q < 8; q++) {
            float v = sc[node * 8 + q];
            #pragma unroll
            for (int cc = 0; cc < 8; cc++) acc[cc] += v * sW[(32 + q) * 64 + c0 + cc];
        }
        float* o = g_x + node * HH + c0;
        *(float4*)o = make_float4(acc[0], acc[1], acc[2], acc[3]);
        *(float4*)(o + 4) = make_float4(acc[4], acc[5], acc[6], acc[7]);
    }
}

// ---- tensor-core esm GEMM: x[:,64:128] = esm @ W_esm + b, split-bf16 3-mma ----
__global__ void __launch_bounds__(256) k_esm_tc(const float* __restrict__ esm,
                                                const float* __restrict__ W,
                                                const float* __restrict__ b) {
    __shared__ __nv_bfloat16 AsH[128 * 40];
    __shared__ __nv_bfloat16 AsL[128 * 40];
    __shared__ __nv_bfloat16 BsH[32 * 72];
    __shared__ __nv_bfloat16 BsL[32 * 72];
    int tid = threadIdx.x;
    int m0 = blockIdx.x * 128;
    int wid = tid >> 5, lane = tid & 31;
    int warp_m = wid & 3, warp_n = wid >> 2;

    int arow = tid >> 1, ahalf = tid & 1;
    int grow = m0 + arow; if (grow >= NN) grow = NN - 1;
    const float* aptr = esm + (size_t)grow * 1280 + ahalf * 16;
    int brow = tid >> 3, bcol = (tid & 7) * 8;
    const float* bptr = W + brow * 64 + bcol;

    float acc[2][4][4];
    #pragma unroll
    for (int a_ = 0; a_ < 2; a_++)
        #pragma unroll
        for (int b_ = 0; b_ < 4; b_++)
            #pragma unroll
            for (int q = 0; q < 4; q++) acc[a_][b_][q] = 0.f;

    float4 ra[4]; float4 rb[2];
    #pragma unroll
    for (int q = 0; q < 4; q++) ra[q] = *(const float4*)(aptr + q * 4);
    rb[0] = *(const float4*)bptr; rb[1] = *(const float4*)(bptr + 4);

    int a_r = lane & 15;
    int a_c = (lane >> 4) * 8;
    int b_k = lane & 15;
    int b_n = (lane >> 4) * 8;

    for (int c = 0; c < 40; c++) {
        {
            float av[16] = {ra[0].x, ra[0].y, ra[0].z, ra[0].w,
                            ra[1].x, ra[1].y, ra[1].z, ra[1].w,
                            ra[2].x, ra[2].y, ra[2].z, ra[2].w,
                            ra[3].x, ra[3].y, ra[3].z, ra[3].w};
            __nv_bfloat162* dH = (__nv_bfloat162*)(AsH + arow * 40 + ahalf * 16);
            __nv_bfloat162* dL = (__nv_bfloat162*)(AsL + arow * 40 + ahalf * 16);
            #pragma unroll
            for (int q = 0; q < 8; q++) {
                __nv_bfloat162 h, l;
                split2(av[2 * q], av[2 * q + 1], h, l);
                dH[q] = h; dL[q] = l;
            }
            float bv[8] = {rb[0].x, rb[0].y, rb[0].z, rb[0].w,
                           rb[1].x, rb[1].y, rb[1].z, rb[1].w};
            __nv_bfloat162* eH = (__nv_bfloat162*)(BsH + brow * 72 + bcol);
            __nv_bfloat162* eL = (__nv_bfloat162*)(BsL + brow * 72 + bcol);
            #pragma unroll
            for (int q = 0; q < 4; q++) {
                __nv_bfloat162 h, l;
                split2(bv[2 * q], bv[2 * q + 1], h, l);
                eH[q] = h; eL[q] = l;
            }
        }
        __syncthreads();
        if (c < 39) {
            aptr += 32; bptr += 32 * 64;
            #pragma unroll
            for (int q = 0; q < 4; q++) ra[q] = *(const float4*)(aptr + q * 4);
            rb[0] = *(const float4*)bptr; rb[1] = *(const float4*)(bptr + 4);
        }
        #pragma unroll
        for (int ks = 0; ks < 2; ks++) {
            unsigned ah[2][4], al[2][4], bh[2][4], bl[2][4];
            #pragma unroll
            for (int mt = 0; mt < 2; mt++) {
                int row = warp_m * 32 + mt * 16 + a_r;
                int col = ks * 16 + a_c;
                LDSM4(ah[mt][0], ah[mt][1], ah[mt][2], ah[mt][3], sptr(AsH + row * 40 + col));
                LDSM4(al[mt][0], al[mt][1], al[mt][2], al[mt][3], sptr(AsL + row * 40 + col));
            }
            #pragma unroll
            for (int g = 0; g < 2; g++) {
                int kk = ks * 16 + b_k;
                int nn = warp_n * 32 + g * 16 + b_n;
                LDSM4T(bh[g][0], bh[g][1], bh[g][2], bh[g][3], sptr(BsH + kk * 72 + nn));
                LDSM4T(bl[g][0], bl[g][1], bl[g][2], bl[g][3], sptr(BsL + kk * 72 + nn));
            }
            #pragma unroll
            for (int mt = 0; mt < 2; mt++)
                #pragma unroll
                for (int nt = 0; nt < 4; nt++) {
                    int g = nt >> 1, h = (nt & 1) * 2;
                    MMA16816(acc[mt][nt], ah[mt][0], ah[mt][1], ah[mt][2], ah[mt][3],
                             bh[g][h], bh[g][h + 1]);
                    MMA16816(acc[mt][nt], ah[mt][0], ah[mt][1], ah[mt][2], ah[mt][3],
                             bl[g][h], bl[g][h + 1]);
                    MMA16816(acc[mt][nt], al[mt][0], al[mt][1], al[mt][2], al[mt][3],
                             bh[g][h], bh[g][h + 1]);
                }
        }
        __syncthreads();
    }
    #pragma unroll
    for (int mt = 0; mt < 2; mt++)
        #pragma unroll
        for (int nt = 0; nt < 4; nt++) {
            int row = m0 + warp_m * 32 + mt * 16 + (lane >> 2);
            int col = warp_n * 32 + nt * 8 + (lane & 3) * 2;
            if (row < NN) {
                g_x[row * HH + 64 + col] = acc[mt][nt][0] + b[col];
                g_x[row * HH + 64 + col + 1] = acc[mt][nt][1] + b[col + 1];
            }
            if (row + 8 < NN) {
                g_x[(row + 8) * HH + 64 + col] = acc[mt][nt][2] + b[col];
                g_x[(row + 8) * HH + 64 + col + 1] = acc[mt][nt][3] + b[col + 1];
            }
        }
}

// ---- tensor-core [N,128]@[128,128] with epilogue, split-bf16 3-mma ----
// EPI0: xm=swish(x@W)  EPI1: xe=x+swish(agg@W)  EPI2: h0=relu(xe@W+b)
template <int EPI>
__global__ void __launch_bounds__(256) k_gemm128_tc(const float* __restrict__ W,
                                                    const float* __restrict__ bias) {
    extern __shared__ __align__(16) char smraw[];
    __nv_bfloat16* AsH = (__nv_bfloat16*)smraw;
    __nv_bfloat16* AsL = AsH + 128 * 136;
    __nv_bfloat16* BsH = AsL + 128 * 136;
    __nv_bfloat16* BsL = BsH + 128 * 136;
    int tid = threadIdx.x;
    int m0 = blockIdx.x * 128;
    int wid = tid >> 5, lane = tid & 31;
    int warp_m = wid & 3, warp_n = wid >> 2;
    const float* A = (EPI == 0) ? g_x : (EPI == 1) ? g_agg : g_xm;
    float* O = (EPI == 2) ? g_agg : g_xm;

    {
        int row = tid >> 1, half = tid & 1;
        int grow = m0 + row; if (grow >= NN) grow = NN - 1;
        const float* ap = A + grow * HH + half * 64;
        __nv_bfloat162* dH = (__nv_bfloat162*)(AsH + row * 136 + half * 64);
        __nv_bfloat162* dL = (__nv_bfloat162*)(AsL + row * 136 + half * 64);
        const float* wp = W + row * 128 + half * 64;
        __nv_bfloat162* eH = (__nv_bfloat162*)(BsH + row * 136 + half * 64);
        __nv_bfloat162* eL = (__nv_bfloat162*)(BsL + row * 136 + half * 64);
        #pragma unroll
        for (int q = 0; q < 16; q++) {
            float4 v = ((const float4*)ap)[q];
            __nv_bfloat162 h, l;
            split2(v.x, v.y, h, l); dH[2 * q] = h; dL[2 * q] = l;
            split2(v.z, v.w, h, l); dH[2 * q + 1] = h; dL[2 * q + 1] = l;
            float4 w = ((const float4*)wp)[q];
            split2(w.x, w.y, h, l); eH[2 * q] = h; eL[2 * q] = l;
            split2(w.z, w.w, h, l); eH[2 * q + 1] = h; eL[2 * q + 1] = l;
        }
    }
    __syncthreads();

    float acc[2][8][4];
    #pragma unroll
    for (int a_ = 0; a_ < 2; a_++)
        #pragma unroll
        for (int b_ = 0; b_ < 8; b_++)
            #pragma unroll
            for (int q = 0; q < 4; q++) acc[a_][b_][q] = 0.f;

    int a_r = lane & 15, a_c = (lane >> 4) * 8;
    int b_k = lane & 15, b_n = (lane >> 4) * 8;
    #pragma unroll
    for (int ks = 0; ks < 8; ks++) {
        unsigned ah[2][4], al[2][4];
        #pragma unroll
        for (int mt = 0; mt < 2; mt++) {
            int row = warp_m * 32 + mt * 16 + a_r;
            int col = ks * 16 + a_c;
            LDSM4(ah[mt][0], ah[mt][1], ah[mt][2], ah[mt][3], sptr(AsH + row * 136 + col));
            LDSM4(al[mt][0], al[mt][1], al[mt][2], al[mt][3], sptr(AsL + row * 136 + col));
        }
        #pragma unroll
        for (int g = 0; g < 4; g++) {
            unsigned bh[4], bl[4];
            int kk = ks * 16 + b_k;
            int nn = warp_n * 64 + g * 16 + b_n;
            LDSM4T(bh[0], bh[1], bh[2], bh[3], sptr(BsH + kk * 136 + nn));
            LDSM4T(bl[0], bl[1], bl[2], bl[3], sptr(BsL + kk * 136 + nn));
            #pragma unroll
            for (int mt = 0; mt < 2; mt++)
                #pragma unroll
                for (int t8 = 0; t8 < 2; t8++) {
                    int h = t8 * 2;
                    float* d = acc[mt][g * 2 + t8];
                    MMA16816(d, ah[mt][0], ah[mt][1], ah[mt][2], ah[mt][3], bh[h], bh[h + 1]);
                    MMA16816(d, ah[mt][0], ah[mt][1], ah[mt][2], ah[mt][3], bl[h], bl[h + 1]);
                    MMA16816(d, al[mt][0], al[mt][1], al[mt][2], al[mt][3], bh[h], bh[h + 1]);
                }
        }
    }
    #pragma unroll
    for (int mt = 0; mt < 2; mt++)
        #pragma unroll
        for (int nt = 0; nt < 8; nt++) {
            int row = m0 + warp_m * 32 + mt * 16 + (lane >> 2);
            int col = warp_n * 64 + nt * 8 + (lane & 3) * 2;
            float* d = acc[mt][nt];
            #pragma unroll
            for (int rr = 0; rr < 2; rr++) {
                int r = row + rr * 8;
                if (r < NN) {
                    float v0 = d[rr * 2], v1 = d[rr * 2 + 1];
                    float o0, o1;
                    if (EPI == 2) {
                        o0 = fmaxf(v0 + bias[col], 0.f);
                        o1 = fmaxf(v1 + bias[col + 1], 0.f);
                    } else if (EPI == 1) {
                        float2 xv = *(const float2*)(g_x + r * HH + col);
                        o0 = xv.x + swishf(v0);
                        o1 = xv.y + swishf(v1);
                    } else {
                        o0 = swishf(v0);
                        o1 = swishf(v1);
                    }
                    *(float2*)(O + r * HH + col) = make_float2(o0, o1);
                }
            }
        }
}

// shared scatter for edge mma epilogues
__device__ __forceinline__ void edge_scatter(float acc[2][8][4], const int* js, const int* is_,
                                             int warp_m, int warp_n, int lane) {
    #pragma unroll
    for (int mt = 0; mt < 2; mt++)
        #pragma unroll
        for (int nt = 0; nt < 8; nt++) {
            int el = warp_m * 32 + mt * 16 + (lane >> 2);
            int col = warp_n * 64 + nt * 8 + (lane & 3) * 2;
            float* d = acc[mt][nt];
            #pragma unroll
            for (int rr = 0; rr < 2; rr++) {
                int e = el + rr * 8;
                int j = js[e];
                if (j >= 0) {
                    int i = is_[e];
                    float2 xv = *(const float2*)(g_xm + j * HH + col);
                    float m0 = swishf(d[rr * 2]) * xv.x;
                    float m1 = swishf(d[rr * 2 + 1]) * xv.y;
                    asm volatile("red.global.add.v2.f32 [%0], {%1,%2};"
                                 :: "l"(g_agg + i * HH + col), "f"(m0), "f"(m1) : "memory");
                }
            }
        }
}

// near edges: full 124-feature path, 128 edges/block, tensor-core GEMM
__global__ void __launch_bounds__(256) k_edge_near_tc(const float* __restrict__ pos,
                                                      const float* __restrict__ posn,
                                                      const float* __restrict__ posc,
                                                      const float* __restrict__ We) {
    int cnt = g_ncnt;
    if (blockIdx.x * 128 >= cnt) return;
    extern __shared__ __align__(16) char smraw[];
    __nv_bfloat16* WsH = (__nv_bfloat16*)smraw;
    __nv_bfloat16* WsL = WsH + 128 * 136;
    __nv_bfloat16* FsH = WsL + 128 * 136;
    __nv_bfloat16* FsL = FsH + 128 * 136;
    int* js = (int*)(FsL + 128 * 136);
    int* is_ = js + 128;
    float* freqs = (float*)(is_ + 128);
    int tid = threadIdx.x;
    int wid = tid >> 5, lane = tid & 31;
    int warp_m = wid & 3, warp_n = wid >> 2;

    {   // load W_edge [124][128] -> bf16 hi/lo, zero-pad k rows 124..127
        int krow = tid >> 1, half = tid & 1;
        __nv_bfloat162* eH = (__nv_bfloat162*)(WsH + krow * 136 + half * 64);
        __nv_bfloat162* eL = (__nv_bfloat162*)(WsL + krow * 136 + half * 64);
        if (krow < 124) {
            const float* wp = We + krow * 128 + half * 64;
            #pragma unroll
            for (int q = 0; q < 16; q++) {
                float4 w = ((const float4*)wp)[q];
                __nv_bfloat162 h, l;
                split2(w.x, w.y, h, l); eH[2 * q] = h; eL[2 * q] = l;
                split2(w.z, w.w, h, l); eH[2 * q + 1] = h; eL[2 * q + 1] = l;
            }
        } else {
            __nv_bfloat162 zz = __halves2bfloat162(__float2bfloat16_rn(0.f), __float2bfloat16_rn(0.f));
            #pragma unroll
            for (int q = 0; q < 32; q++) { eH[q] = zz; eL[q] = zz; }
        }
    }
    if (tid < 8) {
        float t = (float)(2 * tid) * (float)(-0.5756462732485115);
        freqs[tid] = (float)exp((double)t);
    }
    __syncthreads();

    if (tid < 128) {
        int idx = blockIdx.x * 128 + tid;
        bool valid = idx < cnt;
        int2 ji = g_nJI[valid ? idx : cnt - 1];
        int j = ji.x, i = ji.y;
        js[tid] = valid ? j : -1;
        is_[tid] = i;
        __nv_bfloat16* fH = FsH + tid * 136;
        __nv_bfloat16* fL = FsL + tid * 136;
        F3 pi_ = ld3(pos, i), pj = ld3(pos, j);
        F3 vji = sub3(pj, pi_);
        float dist = sqrtf(dot3(vji, vji));
        int r0 = (i == 0) ? NN - 1 : i - 1;
        int r1 = (i == NN - 1) ? 0 : i + 1;
        F3 vr0 = sub3(ld3(pos, r0), pi_);
        F3 vr1 = sub3(ld3(pos, r1), pi_);
        float a = dot3(vji, vr0);
        F3 cr = crs3(vji, vr0);
        float b2 = dot3(cr, cr);
        float ct1 = a * rsqrtf(fmaxf(a * a + b2, 1e-30f));
        float ct2 = 2.f * ct1 * ct1 - 1.f;
        F3 p1 = crs3(vr0, vr1), p2 = crs3(vr0, vji);
        float ap = dot3(p1, p2);
        F3 c12 = crs3(p1, p2);
        float bp = dot3(c12, vr0) / (sqrtf(dot3(vr0, vr0)) + 1e-7f);
        float cp1 = ap * rsqrtf(fmaxf(ap * ap + bp * bp, 1e-30f));
        float cp2 = 2.f * cp1 * cp1 - 1.f;
        F3 o1x = sub3(ld3(posn, i), pi_);
        F3 o1z = crs3(o1x, crs3(o1x, sub3(ld3(posc, i), pi_)));
        float o1zl = sqrtf(dot3(o1z, o1z)) + 1e-7f;
        F3 o2x = sub3(ld3(posn, j), pj);
        F3 o2z = crs3(o2x, crs3(o2x, sub3(ld3(posc, j), pj)));
        float o2zl = sqrtf(dot3(o2z, o2z)) + 1e-7f;
        F3 nv = crs3(o1z, o2z);
        float a1 = dot3(o1x, nv);
        float b1 = dot3(crs3(o1x, nv), o1z) / o1zl;
        float cA10 = a1 * rsqrtf(fmaxf(a1 * a1 + b1 * b1, 1e-30f));
        float cA11 = 2.f * cA10 * cA10 - 1.f;
        float a2 = dot3(o1z, o2z);
        float b2v = sqrtf(dot3(nv, nv));
        float cA20 = a2 * rsqrtf(fmaxf(a2 * a2 + b2v * b2v, 1e-30f));
        float cA21 = 2.f * cA20 * cA20 - 1.f;
        float a3 = dot3(nv, o2x);
        float b3 = dot3(crs3(nv, o2x), o2z) / o2zl;
        float cA30 = a3 * rsqrtf(fmaxf(a3 * a3 + b3 * b3, 1e-30f));
        float cA31 = 2.f * cA30 * cA30 - 1.f;
        float u = fminf(dist / 11.5f, 1.f);
        float fc = 0.5f * (cosf(3.14159274f * u) + 1.f);
        float rs = (float)0.41702882811414954 * fc / (dist + 1e-6f);
        float r[6];
        #pragma unroll
        for (int n = 0; n < 6; n++)
            r[n] = rs * sinf((float)(n + 1) * 3.14159274f * u);
        float ct[3] = {1.f, ct1, ct2};
        float cp[3] = {1.f, cp1, cp2};
        #pragma unroll
        for (int n = 0; n < 6; n++)
            #pragma unroll
            for (int l = 0; l < 3; l++) {
                float rl = r[n] * ct[l];
                #pragma unroll
                for (int m = 0; m < 3; m++) {
                    int k = n * 9 + l * 3 + m;
                    split1(rl * cp[m], fH + k, fL + k);
                }
            }
        float cA[3][3] = {{1.f, cA10, cA11}, {1.f, cA20, cA21}, {1.f, cA30, cA31}};
        #pragma unroll
        for (int t = 0; t < 3; t++)
            #pragma unroll
            for (int n = 0; n < 6; n++)
                #pragma unroll
                for (int l = 0; l < 3; l++) {
                    int k = 54 + t * 18 + n * 3 + l;
                    split1(r[n] * cA[t][l], fH + k, fL + k);
                }
        float dpe = (float)(j - i);
        #pragma unroll
        for (int kk = 0; kk < 8; kk++) {
            float s, c;
            sincosf(dpe * freqs[kk], &s, &c);
            split1(c, fH + 108 + kk, fL + 108 + kk);
            split1(s, fH + 116 + kk, fL + 116 + kk);
        }
        __nv_bfloat16 zb = __float2bfloat16_rn(0.f);
        #pragma unroll
        for (int k = 124; k < 128; k++) { fH[k] = zb; fL[k] = zb; }
    }
    __syncthreads();

    float acc[2][8][4];
    #pragma unroll
    for (int a_ = 0; a_ < 2; a_++)
        #pragma unroll
        for (int b_ = 0; b_ < 8; b_++)
            #pragma unroll
            for (int q = 0; q < 4; q++) acc[a_][b_][q] = 0.f;
    int a_r = lane & 15, a_c = (lane >> 4) * 8;
    int b_k = lane & 15, b_n = (lane >> 4) * 8;
    #pragma unroll
    for (int ks = 0; ks < 8; ks++) {
        unsigned ah[2][4], al[2][4];
        #pragma unroll
        for (int mt = 0; mt < 2; mt++) {
            int row = warp_m * 32 + mt * 16 + a_r;
            int col = ks * 16 + a_c;
            LDSM4(ah[mt][0], ah[mt][1], ah[mt][2], ah[mt][3], sptr(FsH + row * 136 + col));
            LDSM4(al[mt][0], al[mt][1], al[mt][2], al[mt][3], sptr(FsL + row * 136 + col));
        }
        #pragma unroll
        for (int g = 0; g < 4; g++) {
            unsigned bh[4], bl[4];
            int kk = ks * 16 + b_k;
            int nn = warp_n * 64 + g * 16 + b_n;
            LDSM4T(bh[0], bh[1], bh[2], bh[3], sptr(WsH + kk * 136 + nn));
            LDSM4T(bl[0], bl[1], bl[2], bl[3], sptr(WsL + kk * 136 + nn));
            #pragma unroll
            for (int mt = 0; mt < 2; mt++)
                #pragma unroll
                for (int t8 = 0; t8 < 2; t8++) {
                    int h = t8 * 2;
                    float* d = acc[mt][g * 2 + t8];
                    MMA16816(d, ah[mt][0], ah[mt][1], ah[mt][2], ah[mt][3], bh[h], bh[h + 1]);
                    MMA16816(d, ah[mt][0], ah[mt][1], ah[mt][2], ah[mt][3], bl[h], bl[h + 1]);
                    MMA16816(d, al[mt][0], al[mt][1], al[mt][2], al[mt][3], bh[h], bh[h + 1]);
                }
        }
    }
    edge_scatter(acc, js, is_, warp_m, warp_n, lane);
}

// far edges: only 16 pe features nonzero, 128 edges/block, tensor-core GEMM
__global__ void __launch_bounds__(256) k_edge_far_tc(const float* __restrict__ We) {
    int cnt = g_fcnt;
    if (blockIdx.x * 128 >= cnt) return;
    __shared__ __nv_bfloat16 WsH[16 * 136], WsL[16 * 136];
    __shared__ __nv_bfloat16 FsH[128 * 24], FsL[128 * 24];
    __shared__ int js[128], is_[128];
    __shared__ float freqs[8];
    int tid = threadIdx.x;
    int wid = tid >> 5, lane = tid & 31;
    int warp_m = wid & 3, warp_n = wid >> 2;

    {   // W_edge rows 108..123 -> 16 x 128
        int krow = tid >> 4, ncol = (tid & 15) * 8;
        const float* wp = We + (108 + krow) * 128 + ncol;
        __nv_bfloat162* eH = (__nv_bfloat162*)(WsH + krow * 136 + ncol);
        __nv_bfloat162* eL = (__nv_bfloat162*)(WsL + krow * 136 + ncol);
        #pragma unroll
        for (int q = 0; q < 2; q++) {
            float4 w = ((const float4*)wp)[q];
            __nv_bfloat162 h, l;
            split2(w.x, w.y, h, l); eH[2 * q] = h; eL[2 * q] = l;
            split2(w.z, w.w, h, l); eH[2 * q + 1] = h; eL[2 * q + 1] = l;
        }
    }
    if (tid < 8) {
        float t = (float)(2 * tid) * (float)(-0.5756462732485115);
        freqs[tid] = (float)exp((double)t);
    }
    __syncthreads();
    if (tid < 128) {
        int idx = blockIdx.x * 128 + tid;
        bool valid = idx < cnt;
        int2 ji = g_fJI[valid ? idx : cnt - 1];
        int j = ji.x, i = ji.y;
        js[tid] = valid ? j : -1;
        is_[tid] = i;
        float dpe = (float)(j - i);
        __nv_bfloat16* fH = FsH + tid * 24;
        __nv_bfloat16* fL = FsL + tid * 24;
        #pragma unroll
        for (int kk = 0; kk < 8; kk++) {
            float s, c;
            sincosf(dpe * freqs[kk], &s, &c);
            split1(c, fH + kk, fL + kk);
            split1(s, fH + 8 + kk, fL + 8 + kk);
        }
    }
    __syncthreads();

    float acc[2][8][4];
    #pragma unroll
    for (int a_ = 0; a_ < 2; a_++)
        #pragma unroll
        for (int b_ = 0; b_ < 8; b_++)
            #pragma unroll
            for (int q = 0; q < 4; q++) acc[a_][b_][q] = 0.f;
    int a_r = lane & 15, a_c = (lane >> 4) * 8;
    int b_k = lane & 15, b_n = (lane >> 4) * 8;
    unsigned ah[2][4], al[2][4];
    #pragma unroll
    for (int mt = 0; mt < 2; mt++) {
        int row = warp_m * 32 + mt * 16 + a_r;
        LDSM4(ah[mt][0], ah[mt][1], ah[mt][2], ah[mt][3], sptr(FsH + row * 24 + a_c));
        LDSM4(al[mt][0], al[mt][1], al[mt][2], al[mt][3], sptr(FsL + row * 24 + a_c));
    }
    #pragma unroll
    for (int g = 0; g < 4; g++) {
        unsigned bh[4], bl[4];
        int nn = warp_n * 64 + g * 16 + b_n;
        LDSM4T(bh[0], bh[1], bh[2], bh[3], sptr(WsH + b_k * 136 + nn));
        LDSM4T(bl[0], bl[1], bl[2], bl[3], sptr(WsL + b_k * 136 + nn));
        #pragma unroll
        for (int mt = 0; mt < 2; mt++)
            #pragma unroll
            for (int t8 = 0; t8 < 2; t8++) {
                int h = t8 * 2;
                float* d = acc[mt][g * 2 + t8];
                MMA16816(d, ah[mt][0], ah[mt][1], ah[mt][2], ah[mt][3], bh[h], bh[h + 1]);
                MMA16816(d, ah[mt][0], ah[mt][1], ah[mt][2], ah[mt][3], bl[h], bl[h + 1]);
                MMA16816(d, al[mt][0], al[mt][1], al[mt][2], al[mt][3], bh[h], bh[h + 1]);
            }
    }
    edge_scatter(acc, js, is_, warp_m, warp_n, lane);
}

// node head: one warp per node
__global__ void __launch_bounds__(256) k_nodehead(const float* __restrict__ W0,
                                                  const float* __restrict__ b0,
                                                  const float* __restrict__ Wf,
                                                  const float* __restrict__ bf,
                                                  float* __restrict__ out2) {
    __shared__ float sW[4096];
    __shared__ float sb[32], sWf[64], sbf[2];
    int tid = threadIdx.x;
    for (int idx = tid; idx < 4096; idx += 256) sW[idx] = W0[idx];
    if (tid < 32) sb[tid] = b0[tid];
    if (tid < 64) sWf[tid] = Wf[tid];
    if (tid < 2) sbf[tid] = bf[tid];
    __syncthreads();
    int w = tid >> 5, lane = tid & 31;
    int n = blockIdx.x * 8 + w;
    if (n >= NN) return;
    const float* xr = g_x + n * HH;
    float acc = sb[lane];
    #pragma unroll 8
    for (int k = 0; k < 128; k++) acc += xr[k] * sW[k * 32 + lane];
    float xn = fmaxf(acc, 0.f);
    float v0 = xn * sWf[lane * 2], v1 = xn * sWf[lane * 2 + 1];
    #pragma unroll
    for (int off = 16; off > 0; off >>= 1) {
        v0 += __shfl_xor_sync(0xffffffffu, v0, off);
        v1 += __shfl_xor_sync(0xffffffffu, v1, off);
    }
    if (lane == 0) { out2[n * 2] = v0 + sbf[0]; out2[n * 2 + 1] = v1 + sbf[1]; }
}

// final head: out = sigmoid(relu(h0@W_o1+b)@W_of+b)
__global__ void __launch_bounds__(256) k_final(const float* __restrict__ W1,
                                               const float* __restrict__ b1,
                                               const float* __restrict__ Wf,
                                               const float* __restrict__ bf,
                                               float* __restrict__ out) {
    __shared__ float sW[4096];
    __shared__ float sb[32], sWf[32];
    int tid = threadIdx.x;
    for (int idx = tid; idx < 4096; idx += 256) sW[idx] = W1[idx];
    if (tid < 32) { sb[tid] = b1[tid]; sWf[tid] = Wf[tid]; }
    __syncthreads();
    int w = tid >> 5, lane = tid & 31;
    int n = blockIdx.x * 8 + w;
    if (n >= NN) return;
    const float* hr = g_agg + n * HH;
    float acc = sb[lane];
    #pragma unroll 8
    for (int k = 0; k < 128; k++) acc += hr[k] * sW[k * 32 + lane];
    float v = fmaxf(acc, 0.f) * sWf[lane];
    #pragma unroll
    for (int off = 16; off > 0; off >>= 1) v += __shfl_xor_sync(0xffffffffu, v, off);
    if (lane == 0) out[n] = 1.f / (1.f + expf(-(v + bf[0])));
}

extern "C" void kernel_launch(void* const* d_in, const int* in_sizes, int n_in,
                              void* d_out, int out_size) {
    const int* z = (const int*)d_in[0];
    const float* pos = (const float*)d_in[1];
    const float* posn = (const float*)d_in[2];
    const float* posc = (const float*)d_in[3];
    const float* bb = (const float*)d_in[4];
    const float* sc = (const float*)d_in[5];
    const float* esm = (const float*)d_in[6];
    const int* ei = (const int*)d_in[8];
    const float* W_emb = (const float*)d_in[9];
    const float* b_emb = (const float*)d_in[10];
    const float* W_esm = (const float*)d_in[11];
    const float* b_esm = (const float*)d_in[12];
    const float* W_edge = (const float*)d_in[13];
    const float* W_msg = (const float*)d_in[14];
    const float* W_upd = (const float*)d_in[15];
    const float* W_o0 = (const float*)d_in[16];
    const float* b_o0 = (const float*)d_in[17];
    const float* W_o1 = (const float*)d_in[18];
    const float* b_o1 = (const float*)d_in[19];
    const float* W_of = (const float*)d_in[20];
    const float* b_of = (const float*)d_in[21];
    const float* W_n0 = (const float*)d_in[22];
    const float* b_n0 = (const float*)d_in[23];
    const float* W_nf = (const float*)d_in[24];
    const float* b_nf = (const float*)d_in[25];
    float* out = (float*)d_out;

    const int GEMM_SMEM = 4 * 128 * 136 * 2;            // 139264
    const int NEAR_SMEM = 4 * 128 * 136 * 2 + 2 * 128 * 4 + 32;  // 140320
    static bool attr_done = false;
    if (!attr_done) {
        cudaFuncSetAttribute(k_gemm128_tc<0>, cudaFuncAttributeMaxDynamicSharedMemorySize, GEMM_SMEM);
        cudaFuncSetAttribute(k_gemm128_tc<1>, cudaFuncAttributeMaxDynamicSharedMemorySize, GEMM_SMEM);
        cudaFuncSetAttribute(k_gemm128_tc<2>, cudaFuncAttributeMaxDynamicSharedMemorySize, GEMM_SMEM);
        cudaFuncSetAttribute(k_edge_near_tc, cudaFuncAttributeMaxDynamicSharedMemorySize, NEAR_SMEM);
        attr_done = true;
    }

    k_zero<<<6250, 256>>>();
    k_classify<<<3907, 256>>>(ei, pos);
    k_embed<<<1563, 256>>>(z, bb, sc, W_emb, b_emb);
    k_esm_tc<<<391, 256>>>(esm, W_esm, b_esm);
    k_gemm128_tc<0><<<391, 256, GEMM_SMEM>>>(W_msg, nullptr);
    k_edge_near_tc<<<7813, 256, NEAR_SMEM>>>(pos, posn, posc, W_edge);
    k_edge_far_tc<<<7813, 256>>>(W_edge);
    k_gemm128_tc<1><<<391, 256, GEMM_SMEM>>>(W_upd, nullptr);
    k_gemm128_tc<2><<<391, 256, GEMM_SMEM>>>(W_o0, b_o0);
    k_nodehead<<<6250, 256>>>(W_n0, b_n0, W_nf, b_nf, out + NN);
    k_final<<<6250, 256>>>(W_o1, b_o1, W_of, b_of, out);
}